// round 11
// baseline (speedup 1.0000x reference)
#include <cuda_runtime.h>
#include <cuda_bf16.h>
#include <math.h>
#include <stdint.h>

#define Bb    8
#define Cc    256
#define HW    4096
#define PER_B (Cc * HW)          // 2^20
#define EPSF  1e-12f

// ---------------- device scratch ----------------
__device__ float g_Q[7][Bb * PER_B];   // unnormalized Krylov vectors fp32, slots 1..7 (slot 0 = input v)
__device__ __nv_bfloat16 g_Qbf[8][Bb * PER_B]; // bf16 mirror of Qu_j (slot 0 = bf16(v)) for dots
__device__ float g_w[Bb * PER_B];      // GEMM output (scaled by inv_k)
__device__ __nv_bfloat16 g_Rhi[Bb * PER_B];  // replicator out, layout [b][c][p] (p contiguous), hi
__device__ __nv_bfloat16 g_Rlo[Bb * PER_B];  // lo residual
__device__ __nv_bfloat16 g_Whi[Cc * Cc];
__device__ __nv_bfloat16 g_Wlo[Cc * Cc];
__device__ float g_dpart[8][Bb][64];   // raw dot partials [j][b][mt*32+pblock]
__device__ float g_npart[Bb][128];     // norm partials
__device__ float g_H[Bb][8][8];
__device__ float g_inv[8][Bb];
__device__ float g_vnorm[Bb];
__device__ float g_cf[Bb][8];

// ---------------- PTX helpers ----------------
static __device__ __forceinline__ uint32_t smem_u32(const void* p) {
    uint32_t a;
    asm("{ .reg .u64 t; cvta.to.shared.u64 t, %1; cvt.u32.u64 %0, t; }" : "=r"(a) : "l"(p));
    return a;
}
#define CP16(dst, src) \
    asm volatile("cp.async.cg.shared.global [%0], [%1], 16;" :: "r"(dst), "l"(src))
#define CP_COMMIT() asm volatile("cp.async.commit_group;" ::: "memory")
#define CP_WAIT0()  asm volatile("cp.async.wait_group 0;" ::: "memory")
#define CP_WAIT1()  asm volatile("cp.async.wait_group 1;" ::: "memory")
#define LDSM4(r0, r1, r2, r3, addr) \
    asm volatile("ldmatrix.sync.aligned.m8n8.x4.shared.b16 {%0,%1,%2,%3}, [%4];" \
        : "=r"(r0), "=r"(r1), "=r"(r2), "=r"(r3) : "r"(addr))
#define LDSM4T(r0, r1, r2, r3, addr) \
    asm volatile("ldmatrix.sync.aligned.m8n8.x4.trans.shared.b16 {%0,%1,%2,%3}, [%4];" \
        : "=r"(r0), "=r"(r1), "=r"(r2), "=r"(r3) : "r"(addr))

static __device__ __forceinline__ void mma_bf16(float* c, const uint32_t* a, const uint32_t* b) {
    asm volatile("mma.sync.aligned.m16n8k16.row.col.f32.bf16.bf16.f32 "
        "{%0,%1,%2,%3}, {%4,%5,%6,%7}, {%8,%9}, {%0,%1,%2,%3};"
        : "+f"(c[0]), "+f"(c[1]), "+f"(c[2]), "+f"(c[3])
        : "r"(a[0]), "r"(a[1]), "r"(a[2]), "r"(a[3]), "r"(b[0]), "r"(b[1]));
}

static __device__ __forceinline__ float warpReduce(float v) {
    #pragma unroll
    for (int off = 16; off > 0; off >>= 1) v += __shfl_xor_sync(0xFFFFFFFFu, v, off);
    return v;
}

static __device__ __forceinline__ uint32_t pack_hi(float a, float b) {
    __nv_bfloat16 ha = __float2bfloat16(a), hb = __float2bfloat16(b);
    return (uint32_t)__bfloat16_as_ushort(ha) | ((uint32_t)__bfloat16_as_ushort(hb) << 16);
}
static __device__ __forceinline__ uint32_t pack_lo(float a, float b) {
    __nv_bfloat16 ha = __float2bfloat16(a), hb = __float2bfloat16(b);
    float la = a - __bfloat162float(ha), lb = b - __bfloat162float(hb);
    __nv_bfloat16 pa = __float2bfloat16(la), pb = __float2bfloat16(lb);
    return (uint32_t)__bfloat16_as_ushort(pa) | ((uint32_t)__bfloat16_as_ushort(pb) << 16);
}

// ---------------- W split to bf16 hi/lo ----------------
__global__ void __launch_bounds__(256) k_splitW(const float* __restrict__ Wm) {
    int i = blockIdx.x * 256 + threadIdx.x;
    float x = Wm[i];
    __nv_bfloat16 h = __float2bfloat16(x);
    g_Whi[i] = h;
    g_Wlo[i] = __float2bfloat16(x - __bfloat162float(h));
}

// ---------------- step-0 replicator: R(v) + Qbf0 + ||v||^2 partials (32p x 256c, 256 thr) ----------------
__global__ void __launch_bounds__(256, 2) k_repl0(const float* __restrict__ s0,
                                                  const float* __restrict__ v) {
    const int t = threadIdx.x, lane = t & 31, wid = t >> 5;
    const int pq = t & 7;           // p-quad (8 quads = 32 p)
    const int cg = t >> 3;          // 0..31 c-groups
    const int b  = blockIdx.y;
    const int p0 = blockIdx.x * 32;
    const size_t base = (size_t)b * PER_B + p0 + pq * 4;

    __shared__ float4 Sred[32][8];
    __shared__ float4 Ssm[8];
    __shared__ float  nsh[8];

    float4 xv[8];
    float4 Sacc = make_float4(0.f, 0.f, 0.f, 0.f);
    float nacc = 0.f;
    #pragma unroll
    for (int i = 0; i < 8; i++) {
        size_t off = base + (size_t)(cg + 32 * i) * HW;
        float4 x4 = *(const float4*)(v + off);
        float4 s4 = *(const float4*)(s0 + off);
        xv[i] = x4;
        Sacc.x += s4.x * x4.x; Sacc.y += s4.y * x4.y;
        Sacc.z += s4.z * x4.z; Sacc.w += s4.w * x4.w;
        nacc += x4.x * x4.x + x4.y * x4.y + x4.z * x4.z + x4.w * x4.w;
    }
    Sred[cg][pq] = Sacc;
    nacc = warpReduce(nacc);
    if (lane == 0) nsh[wid] = nacc;
    __syncthreads();
    if (t < 8) {
        float4 s = make_float4(0.f, 0.f, 0.f, 0.f);
        #pragma unroll
        for (int g2 = 0; g2 < 32; g2++) {
            float4 a = Sred[g2][t];
            s.x += a.x; s.y += a.y; s.z += a.z; s.w += a.w;
        }
        Ssm[t] = s;
    }
    if (t == 8) {
        float s = 0.f;
        #pragma unroll
        for (int w2 = 0; w2 < 8; w2++) s += nsh[w2];
        g_npart[b][blockIdx.x] = s;
    }
    __syncthreads();
    float4 S4 = Ssm[pq];
    #pragma unroll
    for (int i = 0; i < 8; i++) {
        size_t off = base + (size_t)(cg + 32 * i) * HW;
        float4 s4 = *(const float4*)(s0 + off);          // L2-hot
        float rx = s4.x * (xv[i].x - S4.x), ry = s4.y * (xv[i].y - S4.y);
        float rz = s4.z * (xv[i].z - S4.z), rw = s4.w * (xv[i].w - S4.w);
        *(uint2*)(g_Rhi + off)    = make_uint2(pack_hi(rx, ry), pack_hi(rz, rw));
        *(uint2*)(g_Rlo + off)    = make_uint2(pack_lo(rx, ry), pack_lo(rz, rw));
        *(uint2*)(g_Qbf[0] + off) = make_uint2(pack_hi(xv[i].x, xv[i].y), pack_hi(xv[i].z, xv[i].w));
    }
}

// ---------------- fused update + replicator + dots_fin + norm (k = 0..6) ----------------
__global__ void __launch_bounds__(256, 2) k_upd_repl(const float* __restrict__ s0,
                                                     const float* __restrict__ v, int k) {
    const int t = threadIdx.x, lane = t & 31, wid = t >> 5;
    const int pq = t & 7;
    const int cg = t >> 3;
    const int b  = blockIdx.y;
    const int p0 = blockIdx.x * 32;
    const size_t base = (size_t)b * PER_B + p0 + pq * 4;

    __shared__ float  hc[8];
    __shared__ float4 Sred[32][8];
    __shared__ float4 Ssm[8];
    __shared__ float  nsh[8];

    // inline dots finalize: warp j (j<=k<=6, 8 warps) reduces 64 partials -> hcoef
    if (wid <= k) {
        float dv = g_dpart[wid][b][lane] + g_dpart[wid][b][lane + 32];
        dv = warpReduce(dv);
        if (lane == 0) {
            float invj = g_inv[wid][b];
            float h = dv * invj;
            hc[wid] = h * invj;
            if (blockIdx.x == 0) g_H[b][wid][k] = h;
        }
    }
    __syncthreads();

    float4 xv[8];
    #pragma unroll
    for (int i = 0; i < 8; i++) {
        size_t off = base + (size_t)(cg + 32 * i) * HW;
        xv[i] = __ldcs((const float4*)(g_w + off));      // read-once stream
    }
    for (int j = 0; j <= k; j++) {
        const float* __restrict__ Qj = (j == 0) ? v : g_Q[j - 1];
        float cf = hc[j];
        #pragma unroll
        for (int i = 0; i < 8; i++) {
            size_t off = base + (size_t)(cg + 32 * i) * HW;
            float4 q = *(const float4*)(Qj + off);
            xv[i].x -= cf * q.x; xv[i].y -= cf * q.y;
            xv[i].z -= cf * q.z; xv[i].w -= cf * q.w;
        }
    }

    float* __restrict__ qn = g_Q[k];
    __nv_bfloat16* __restrict__ qb = g_Qbf[k + 1];
    float4 Sacc = make_float4(0.f, 0.f, 0.f, 0.f);
    float nacc = 0.f;
    #pragma unroll
    for (int i = 0; i < 8; i++) {
        size_t off = base + (size_t)(cg + 32 * i) * HW;
        *(float4*)(qn + off) = xv[i];
        *(uint2*)(qb + off)  = make_uint2(pack_hi(xv[i].x, xv[i].y), pack_hi(xv[i].z, xv[i].w));
        float4 s4 = *(const float4*)(s0 + off);
        Sacc.x += s4.x * xv[i].x; Sacc.y += s4.y * xv[i].y;
        Sacc.z += s4.z * xv[i].z; Sacc.w += s4.w * xv[i].w;
        nacc += xv[i].x * xv[i].x + xv[i].y * xv[i].y
              + xv[i].z * xv[i].z + xv[i].w * xv[i].w;
    }
    Sred[cg][pq] = Sacc;
    nacc = warpReduce(nacc);
    if (lane == 0) nsh[wid] = nacc;
    __syncthreads();
    if (t < 8) {
        float4 s = make_float4(0.f, 0.f, 0.f, 0.f);
        #pragma unroll
        for (int g2 = 0; g2 < 32; g2++) {
            float4 a = Sred[g2][t];
            s.x += a.x; s.y += a.y; s.z += a.z; s.w += a.w;
        }
        Ssm[t] = s;
    }
    if (t == 8) {
        float s = 0.f;
        #pragma unroll
        for (int w2 = 0; w2 < 8; w2++) s += nsh[w2];
        g_npart[b][blockIdx.x] = s;
    }
    __syncthreads();
    float4 S4 = Ssm[pq];
    #pragma unroll
    for (int i = 0; i < 8; i++) {
        size_t off = base + (size_t)(cg + 32 * i) * HW;
        float4 s4 = *(const float4*)(s0 + off);          // L2-hot re-read
        float rx = s4.x * (xv[i].x - S4.x), ry = s4.y * (xv[i].y - S4.y);
        float rz = s4.z * (xv[i].z - S4.z), rw = s4.w * (xv[i].w - S4.w);
        *(uint2*)(g_Rhi + off) = make_uint2(pack_hi(rx, ry), pack_hi(rz, rw));
        *(uint2*)(g_Rlo + off) = make_uint2(pack_lo(rx, ry), pack_lo(rz, rw));
    }
}

// ---------------- fused GEMM + dots (3-stage pipeline, bf16 dot reads, inline norm finalize) ----------------
static __device__ __forceinline__ void cp_tileA(uint32_t dstbase, const __nv_bfloat16* src,
                                                int kc, int tid) {
    #pragma unroll
    for (int i = 0; i < 2; i++) {
        int x   = tid + (i << 8);     // 0..511 16B chunks
        int row = x >> 2;             // 0..127
        int cb  = (x & 3) << 4;       // 0,16,32,48
        const char* gp = (const char*)(src + (size_t)row * 256 + kc) + cb;
        uint32_t dp = dstbase + (uint32_t)(row * 64 + (cb ^ (((row >> 1) & 3) << 4)));
        CP16(dp, gp);
    }
}
static __device__ __forceinline__ void cp_tileB(uint32_t dstbase, const __nv_bfloat16* srcb,
                                                int kc, int tid) {
    #pragma unroll
    for (int i = 0; i < 2; i++) {
        int x   = tid + (i << 8);     // 0..511
        int row = x >> 4;             // 0..31 (c within chunk)
        int cb  = (x & 15) << 4;      // byte col 0..240
        const char* gp = (const char*)(srcb + (size_t)(kc + row) * HW) + cb;
        CP16(dstbase + (uint32_t)(row * 272 + cb), gp);
    }
}

#define STG_SZ 33792   // per-stage: AH 8192 + AL 8192 + BH 8704 + BL 8704
#define N_STG  3

static __device__ __forceinline__ void load_chunk(uint32_t st, const __nv_bfloat16* Whi,
                                                  const __nv_bfloat16* Wlo,
                                                  const __nv_bfloat16* RhiB,
                                                  const __nv_bfloat16* RloB,
                                                  int kc, int tid) {
    cp_tileA(st,         Whi,  kc, tid);
    cp_tileA(st + 8192,  Wlo,  kc, tid);
    cp_tileB(st + 16384, RhiB, kc, tid);
    cp_tileB(st + 25088, RloB, kc, tid);
    CP_COMMIT();
}

__global__ void __launch_bounds__(256, 2) k_gemm_fused(const float* __restrict__ v,
                                                       int kstep, int write_w) {
    extern __shared__ __align__(128) char smem[];
    const int tid  = threadIdx.x;
    const int wid  = tid >> 5;
    const int lane = tid & 31;
    const int g    = lane >> 2;
    const int q    = lane & 3;
    const int l8   = lane & 7;
    const int g8   = lane >> 3;
    const int wm   = wid >> 2;       // 0..1
    const int wn   = wid & 3;        // 0..3
    const int p0   = blockIdx.x * 128;
    const int mt   = blockIdx.y;
    const int b    = blockIdx.z;

    uint32_t sb = smem_u32(smem);

    const __nv_bfloat16* Whi = g_Whi + (size_t)mt * 128 * 256;
    const __nv_bfloat16* Wlo = g_Wlo + (size_t)mt * 128 * 256;
    const __nv_bfloat16* RhiB = g_Rhi + (size_t)b * PER_B + p0;
    const __nv_bfloat16* RloB = g_Rlo + (size_t)b * PER_B + p0;
    const size_t qtile = (size_t)b * PER_B + (size_t)(mt * 128) * HW + p0;

    // prologue: chunks 0,1 into stages 0,1
    load_chunk(sb,          Whi, Wlo, RhiB, RloB, 0,  tid);
    load_chunk(sb + STG_SZ, Whi, Wlo, RhiB, RloB, 32, tid);

    // inline norm finalize -> inv_k (overlaps prologue loads); 128 partials
    __shared__ float invsh;
    __shared__ float rsh[4];
    if (tid < 128) {
        float val = warpReduce(g_npart[b][tid]);
        if (lane == 0) rsh[wid] = val;
    }
    __syncthreads();
    if (tid == 0) {
        float hn = sqrtf(rsh[0] + rsh[1] + rsh[2] + rsh[3]);
        float iv = (kstep == 0) ? (1.f / hn) : (1.f / (hn + EPSF));
        invsh = iv;
        if (blockIdx.x == 0 && blockIdx.y == 0) {
            g_inv[kstep][b] = iv;
            if (kstep == 0) g_vnorm[b] = hn;
            else            g_H[b][kstep][kstep - 1] = hn;
        }
    }

    float acc[4][4][4];
    #pragma unroll
    for (int i = 0; i < 4; i++)
        #pragma unroll
        for (int j = 0; j < 4; j++)
            #pragma unroll
            for (int e = 0; e < 4; e++) acc[i][j][e] = 0.f;

    const uint32_t aR0 = (uint32_t)(wm * 64 + (g8 & 1) * 8 + l8);
    const uint32_t aK  = (uint32_t)(g8 >> 1) << 4;
    const uint32_t bRow = (uint32_t)(((lane >> 3) & 1) * 8 + l8);
    const uint32_t bCol = (uint32_t)(wn * 64) + ((uint32_t)(lane >> 4)) * 16;

    #pragma unroll
    for (int ci = 0; ci < 8; ci++) {
        if (ci < 7) { CP_WAIT1(); } else { CP_WAIT0(); }
        __syncthreads();   // chunk ci visible to all; stage (ci-1)%3 free for reuse
        if (ci < 6) {
            uint32_t st = sb + (uint32_t)(((ci + 2) % N_STG) * STG_SZ);
            load_chunk(st, Whi, Wlo, RhiB, RloB, (ci + 2) * 32, tid);
        }
        const uint32_t ST = sb + (uint32_t)((ci % N_STG) * STG_SZ);
        const uint32_t AHs = ST, ALs = ST + 8192, BHs = ST + 16384, BLs = ST + 25088;

        #pragma unroll
        for (int kf = 0; kf < 2; kf++) {
            const uint32_t cbA = (uint32_t)(kf * 32) + aK;
            uint32_t ah[4][4], al[4][4], bh[4][2], bl[4][2];
            #pragma unroll
            for (int mf = 0; mf < 4; mf++) {
                uint32_t r  = aR0 + (uint32_t)(mf * 16);
                uint32_t ao = r * 64 + (cbA ^ (((r >> 1) & 3) << 4));
                LDSM4(ah[mf][0], ah[mf][1], ah[mf][2], ah[mf][3], AHs + ao);
                LDSM4(al[mf][0], al[mf][1], al[mf][2], al[mf][3], ALs + ao);
            }
            #pragma unroll
            for (int j2 = 0; j2 < 2; j2++) {
                uint32_t bo = (uint32_t)(kf * 16 + bRow) * 272 + bCol + (uint32_t)(j2 * 32);
                LDSM4T(bh[2*j2][0], bh[2*j2][1], bh[2*j2+1][0], bh[2*j2+1][1], BHs + bo);
                LDSM4T(bl[2*j2][0], bl[2*j2][1], bl[2*j2+1][0], bl[2*j2+1][1], BLs + bo);
            }
            #pragma unroll
            for (int mf = 0; mf < 4; mf++)
                #pragma unroll
                for (int nf = 0; nf < 4; nf++) {
                    mma_bf16(acc[mf][nf], ah[mf], bh[nf]);   // Whi*Rhi
                    mma_bf16(acc[mf][nf], al[mf], bh[nf]);   // Wlo*Rhi
                    mma_bf16(acc[mf][nf], ah[mf], bl[nf]);   // Whi*Rlo
                }
        }
    }

    // scale by inv_k (deferred normalization of q_k)
    const float inv = invsh;
    #pragma unroll
    for (int mf = 0; mf < 4; mf++)
        #pragma unroll
        for (int nf = 0; nf < 4; nf++)
            #pragma unroll
            for (int e = 0; e < 4; e++) acc[mf][nf][e] *= inv;

    if (write_w) {
        float* dst = g_w + qtile;
        #pragma unroll
        for (int mf = 0; mf < 4; mf++) {
            int m = wm * 64 + mf * 16 + g;
            #pragma unroll
            for (int nf = 0; nf < 4; nf++) {
                int pp = wn * 32 + nf * 8 + q * 2;
                __stcs((float2*)(dst + (size_t)m * HW + pp),
                       make_float2(acc[mf][nf][0], acc[mf][nf][1]));
                __stcs((float2*)(dst + (size_t)(m + 8) * HW + pp),
                       make_float2(acc[mf][nf][2], acc[mf][nf][3]));
            }
        }
    }

    // fused dots vs bf16 Q mirror: raw partial <Qbf_j, w> over this CTA's 128x128 tile
    __shared__ float dsh[8][8];
    for (int j = 0; j <= kstep; j++) {
        const __nv_bfloat16* Qb = g_Qbf[j] + qtile;
        float d = 0.f;
        #pragma unroll
        for (int mf = 0; mf < 4; mf++) {
            int m = wm * 64 + mf * 16 + g;
            #pragma unroll
            for (int nf = 0; nf < 4; nf++) {
                int pp = wn * 32 + nf * 8 + q * 2;
                float2 a0 = __bfloat1622float2(*(const __nv_bfloat162*)(Qb + (size_t)m * HW + pp));
                float2 a1 = __bfloat1622float2(*(const __nv_bfloat162*)(Qb + (size_t)(m + 8) * HW + pp));
                d += acc[mf][nf][0] * a0.x + acc[mf][nf][1] * a0.y
                   + acc[mf][nf][2] * a1.x + acc[mf][nf][3] * a1.y;
            }
        }
        d = warpReduce(d);
        if (lane == 0) dsh[j][wid] = d;
    }
    __syncthreads();
    if (tid < 64) {
        int j = tid >> 3, w8 = tid & 7;
        float val = (j <= kstep) ? dsh[j][w8] : 0.f;
        #pragma unroll
        for (int off = 4; off > 0; off >>= 1) val += __shfl_xor_sync(0xFFFFFFFFu, val, off);
        if (w8 == 0 && j <= kstep) g_dpart[j][b][mt * 32 + blockIdx.x] = val;
    }
}

// ---------------- expm of 9x9 (scaling-squaring + Taylor, fp64) + H col 7 finalize ----------------
__global__ void k_expm() {
    const int b = blockIdx.x;
    const int t = threadIdx.x;
    __shared__ double A[81], M[81], P[81], Pn[81];
    __shared__ float Hc7[8];
    __shared__ int ssc;

    if (t < 8) {
        float dv = 0.f;
        for (int i2 = 0; i2 < 64; i2++) dv += g_dpart[t][b][i2];
        Hc7[t] = dv * g_inv[t][b];
    }
    __syncthreads();

    if (t < 81) {
        int i = t / 9, j = t % 9;
        double e = 0.0;
        if (i < 8 && j < 8) e = (j == 7) ? (double)Hc7[i] : (double)g_H[b][i][j];
        if (i == 0 && j == 8) e = 1.0;
        A[t] = e;
    }
    __syncthreads();
    if (t == 0) {
        double nrm = 0.0;
        for (int i = 0; i < 9; i++) {
            double rs = 0.0;
            for (int j = 0; j < 9; j++) rs += fabs(A[i * 9 + j]);
            if (rs > nrm) nrm = rs;
        }
        int s = 0;
        while (nrm > 0.5 && s < 60) { nrm *= 0.5; s++; }
        ssc = s;
    }
    __syncthreads();
    const int s = ssc;
    if (t < 81) {
        A[t] = ldexp(A[t], -s);
        M[t] = ((t % 10 == 0) ? 1.0 : 0.0) + A[t];
        P[t] = A[t];
    }
    __syncthreads();
    for (int it = 2; it <= 22; it++) {
        if (t < 81) {
            int i = t / 9, j = t % 9;
            double acc = 0.0;
            #pragma unroll
            for (int kk = 0; kk < 9; kk++) acc += P[i * 9 + kk] * A[kk * 9 + j];
            Pn[t] = acc / (double)it;
        }
        __syncthreads();
        if (t < 81) { P[t] = Pn[t]; M[t] += P[t]; }
        __syncthreads();
    }
    for (int qq = 0; qq < s; qq++) {
        if (t < 81) {
            int i = t / 9, j = t % 9;
            double acc = 0.0;
            #pragma unroll
            for (int kk = 0; kk < 9; kk++) acc += M[i * 9 + kk] * M[kk * 9 + j];
            Pn[t] = acc;
        }
        __syncthreads();
        if (t < 81) M[t] = Pn[t];
        __syncthreads();
    }
    if (t < 8) {
        double coord = M[t * 9 + 8];
        g_cf[b][t] = (float)(coord * (double)g_vnorm[b] * (double)g_inv[t][b]);
    }
}

// ---------------- final combine (float4, fp32 Q) ----------------
__global__ void __launch_bounds__(256) k_combine(const float* __restrict__ v,
                                                 float* __restrict__ out) {
    int b = blockIdx.y;
    size_t idx = (size_t)b * PER_B + ((size_t)blockIdx.x * 256 + threadIdx.x) * 4;
    float cf[8];
    #pragma unroll
    for (int j = 0; j < 8; j++) cf[j] = g_cf[b][j];
    float4 x = make_float4(0.f, 0.f, 0.f, 0.f);
    #pragma unroll
    for (int j = 0; j < 8; j++) {
        const float* qs = (j == 0) ? v : g_Q[j - 1];
        float4 q = __ldcs((const float4*)(qs + idx));
        x.x += cf[j] * q.x; x.y += cf[j] * q.y;
        x.z += cf[j] * q.z; x.w += cf[j] * q.w;
    }
    *(float4*)(out + idx) = x;
}

// ---------------- driver ----------------
extern "C" void kernel_launch(void* const* d_in, const int* in_sizes, int n_in,
                              void* d_out, int out_size) {
    const float* s0 = (const float*)d_in[0];
    const float* v  = (const float*)d_in[1];
    const float* Wm = (const float*)d_in[2];
    float* out = (float*)d_out;

    const int GEMM_SMEM = N_STG * STG_SZ;   // 101376
    cudaFuncSetAttribute(k_gemm_fused, cudaFuncAttributeMaxDynamicSharedMemorySize, GEMM_SMEM);

    dim3 gP(HW / 32, Bb);            // 128 p-tiles x 8 batches (256-thread streaming kernels)
    dim3 gGemm(HW / 128, 2, Bb);     // 32 p-tiles x 2 m-tiles x 8 batches
    dim3 gComb(PER_B / 1024, Bb);

    k_splitW<<<Cc * Cc / 256, 256>>>(Wm);
    k_repl0<<<gP, 256>>>(s0, v);

    for (int k = 0; k < 8; k++) {
        k_gemm_fused<<<gGemm, 256, GEMM_SMEM>>>(v, k, (k < 7) ? 1 : 0);
        if (k < 7) k_upd_repl<<<gP, 256>>>(s0, v, k);
    }

    k_expm<<<Bb, 128>>>();
    k_combine<<<gComb, 256>>>(v, out);
}

// round 12
// speedup vs baseline: 1.2389x; 1.2389x over previous
#include <cuda_runtime.h>
#include <cuda_bf16.h>
#include <math.h>
#include <stdint.h>

#define Bb    8
#define Cc    256
#define HW    4096
#define PER_B (Cc * HW)          // 2^20
#define EPSF  1e-12f

// ---------------- device scratch ----------------
__device__ float g_Q[7][Bb * PER_B];   // unnormalized Krylov vectors fp32, slots 1..7 (slot 0 = input v)
__device__ __nv_bfloat16 g_Qbf[8][Bb * PER_B]; // bf16 mirror of Qu_j (slot 0 = bf16(v)) for dots
__device__ float g_w[Bb * PER_B];      // GEMM output (scaled by inv_k)
__device__ __nv_bfloat16 g_Rhi[Bb * PER_B];  // replicator out, layout [b][c][p] (p contiguous), hi
__device__ __nv_bfloat16 g_Rlo[Bb * PER_B];  // lo residual
__device__ __nv_bfloat16 g_Whi[Cc * Cc];
__device__ __nv_bfloat16 g_Wlo[Cc * Cc];
__device__ float g_dpart[8][Bb][64];   // raw dot partials [j][b][mt*32+pblock]
__device__ float g_npart[Bb][128];     // norm partials
__device__ float g_H[Bb][8][8];
__device__ float g_inv[8][Bb];
__device__ float g_vnorm[Bb];
__device__ float g_cf[Bb][8];

// ---------------- stream/event infra (created once at load; no device memory) ----------------
namespace {
struct StreamInit {
    cudaStream_t st[4];
    cudaEvent_t  root;
    cudaEvent_t  join[4];
    StreamInit() {
        for (int i = 0; i < 4; i++) cudaStreamCreateWithFlags(&st[i], cudaStreamNonBlocking);
        cudaEventCreateWithFlags(&root, cudaEventDisableTiming);
        for (int i = 0; i < 4; i++) cudaEventCreateWithFlags(&join[i], cudaEventDisableTiming);
    }
};
StreamInit g_si;
}

// ---------------- PTX helpers ----------------
static __device__ __forceinline__ uint32_t smem_u32(const void* p) {
    uint32_t a;
    asm("{ .reg .u64 t; cvta.to.shared.u64 t, %1; cvt.u32.u64 %0, t; }" : "=r"(a) : "l"(p));
    return a;
}
#define CP16(dst, src) \
    asm volatile("cp.async.cg.shared.global [%0], [%1], 16;" :: "r"(dst), "l"(src))
#define CP_COMMIT() asm volatile("cp.async.commit_group;" ::: "memory")
#define CP_WAIT0()  asm volatile("cp.async.wait_group 0;" ::: "memory")
#define LDSM4(r0, r1, r2, r3, addr) \
    asm volatile("ldmatrix.sync.aligned.m8n8.x4.shared.b16 {%0,%1,%2,%3}, [%4];" \
        : "=r"(r0), "=r"(r1), "=r"(r2), "=r"(r3) : "r"(addr))
#define LDSM4T(r0, r1, r2, r3, addr) \
    asm volatile("ldmatrix.sync.aligned.m8n8.x4.trans.shared.b16 {%0,%1,%2,%3}, [%4];" \
        : "=r"(r0), "=r"(r1), "=r"(r2), "=r"(r3) : "r"(addr))

static __device__ __forceinline__ void mma_bf16(float* c, const uint32_t* a, const uint32_t* b) {
    asm volatile("mma.sync.aligned.m16n8k16.row.col.f32.bf16.bf16.f32 "
        "{%0,%1,%2,%3}, {%4,%5,%6,%7}, {%8,%9}, {%0,%1,%2,%3};"
        : "+f"(c[0]), "+f"(c[1]), "+f"(c[2]), "+f"(c[3])
        : "r"(a[0]), "r"(a[1]), "r"(a[2]), "r"(a[3]), "r"(b[0]), "r"(b[1]));
}

static __device__ __forceinline__ float warpReduce(float v) {
    #pragma unroll
    for (int off = 16; off > 0; off >>= 1) v += __shfl_xor_sync(0xFFFFFFFFu, v, off);
    return v;
}

static __device__ __forceinline__ uint32_t pack_hi(float a, float b) {
    __nv_bfloat16 ha = __float2bfloat16(a), hb = __float2bfloat16(b);
    return (uint32_t)__bfloat16_as_ushort(ha) | ((uint32_t)__bfloat16_as_ushort(hb) << 16);
}
static __device__ __forceinline__ uint32_t pack_lo(float a, float b) {
    __nv_bfloat16 ha = __float2bfloat16(a), hb = __float2bfloat16(b);
    float la = a - __bfloat162float(ha), lb = b - __bfloat162float(hb);
    __nv_bfloat16 pa = __float2bfloat16(la), pb = __float2bfloat16(lb);
    return (uint32_t)__bfloat16_as_ushort(pa) | ((uint32_t)__bfloat16_as_ushort(pb) << 16);
}

// ---------------- W split to bf16 hi/lo ----------------
__global__ void __launch_bounds__(256) k_splitW(const float* __restrict__ Wm) {
    int i = blockIdx.x * 256 + threadIdx.x;
    float x = Wm[i];
    __nv_bfloat16 h = __float2bfloat16(x);
    g_Whi[i] = h;
    g_Wlo[i] = __float2bfloat16(x - __bfloat162float(h));
}

// ---------------- step-0 replicator: R(v) + Qbf0 + ||v||^2 partials (32p x 256c, 256 thr) ----------------
__global__ void __launch_bounds__(256, 2) k_repl0(const float* __restrict__ s0,
                                                  const float* __restrict__ v, int b0) {
    const int t = threadIdx.x, lane = t & 31, wid = t >> 5;
    const int pq = t & 7;           // p-quad (8 quads = 32 p)
    const int cg = t >> 3;          // 0..31 c-groups
    const int b  = b0 + blockIdx.y;
    const int p0 = blockIdx.x * 32;
    const size_t base = (size_t)b * PER_B + p0 + pq * 4;

    __shared__ float4 Sred[32][8];
    __shared__ float4 Ssm[8];
    __shared__ float  nsh[8];

    float4 xv[8];
    float4 Sacc = make_float4(0.f, 0.f, 0.f, 0.f);
    float nacc = 0.f;
    #pragma unroll
    for (int i = 0; i < 8; i++) {
        size_t off = base + (size_t)(cg + 32 * i) * HW;
        float4 x4 = *(const float4*)(v + off);
        float4 s4 = *(const float4*)(s0 + off);
        xv[i] = x4;
        Sacc.x += s4.x * x4.x; Sacc.y += s4.y * x4.y;
        Sacc.z += s4.z * x4.z; Sacc.w += s4.w * x4.w;
        nacc += x4.x * x4.x + x4.y * x4.y + x4.z * x4.z + x4.w * x4.w;
    }
    Sred[cg][pq] = Sacc;
    nacc = warpReduce(nacc);
    if (lane == 0) nsh[wid] = nacc;
    __syncthreads();
    if (t < 8) {
        float4 s = make_float4(0.f, 0.f, 0.f, 0.f);
        #pragma unroll
        for (int g2 = 0; g2 < 32; g2++) {
            float4 a = Sred[g2][t];
            s.x += a.x; s.y += a.y; s.z += a.z; s.w += a.w;
        }
        Ssm[t] = s;
    }
    if (t == 8) {
        float s = 0.f;
        #pragma unroll
        for (int w2 = 0; w2 < 8; w2++) s += nsh[w2];
        g_npart[b][blockIdx.x] = s;
    }
    __syncthreads();
    float4 S4 = Ssm[pq];
    #pragma unroll
    for (int i = 0; i < 8; i++) {
        size_t off = base + (size_t)(cg + 32 * i) * HW;
        float4 s4 = *(const float4*)(s0 + off);          // L2-hot
        float rx = s4.x * (xv[i].x - S4.x), ry = s4.y * (xv[i].y - S4.y);
        float rz = s4.z * (xv[i].z - S4.z), rw = s4.w * (xv[i].w - S4.w);
        *(uint2*)(g_Rhi + off)    = make_uint2(pack_hi(rx, ry), pack_hi(rz, rw));
        *(uint2*)(g_Rlo + off)    = make_uint2(pack_lo(rx, ry), pack_lo(rz, rw));
        *(uint2*)(g_Qbf[0] + off) = make_uint2(pack_hi(xv[i].x, xv[i].y), pack_hi(xv[i].z, xv[i].w));
    }
}

// ---------------- fused update + replicator + dots_fin + norm (k = 0..6) ----------------
__global__ void __launch_bounds__(256, 2) k_upd_repl(const float* __restrict__ s0,
                                                     const float* __restrict__ v, int k, int b0) {
    const int t = threadIdx.x, lane = t & 31, wid = t >> 5;
    const int pq = t & 7;
    const int cg = t >> 3;
    const int b  = b0 + blockIdx.y;
    const int p0 = blockIdx.x * 32;
    const size_t base = (size_t)b * PER_B + p0 + pq * 4;

    __shared__ float  hc[8];
    __shared__ float4 Sred[32][8];
    __shared__ float4 Ssm[8];
    __shared__ float  nsh[8];

    // inline dots finalize: warp j (j<=k<=6, 8 warps) reduces 64 partials -> hcoef
    if (wid <= k) {
        float dv = g_dpart[wid][b][lane] + g_dpart[wid][b][lane + 32];
        dv = warpReduce(dv);
        if (lane == 0) {
            float invj = g_inv[wid][b];
            float h = dv * invj;
            hc[wid] = h * invj;
            if (blockIdx.x == 0) g_H[b][wid][k] = h;
        }
    }
    __syncthreads();

    float4 xv[8];
    #pragma unroll
    for (int i = 0; i < 8; i++) {
        size_t off = base + (size_t)(cg + 32 * i) * HW;
        xv[i] = *(const float4*)(g_w + off);
    }
    for (int j = 0; j <= k; j++) {
        const float* __restrict__ Qj = (j == 0) ? v : g_Q[j - 1];
        float cf = hc[j];
        #pragma unroll
        for (int i = 0; i < 8; i++) {
            size_t off = base + (size_t)(cg + 32 * i) * HW;
            float4 q = *(const float4*)(Qj + off);
            xv[i].x -= cf * q.x; xv[i].y -= cf * q.y;
            xv[i].z -= cf * q.z; xv[i].w -= cf * q.w;
        }
    }

    float* __restrict__ qn = g_Q[k];
    __nv_bfloat16* __restrict__ qb = g_Qbf[k + 1];
    float4 Sacc = make_float4(0.f, 0.f, 0.f, 0.f);
    float nacc = 0.f;
    #pragma unroll
    for (int i = 0; i < 8; i++) {
        size_t off = base + (size_t)(cg + 32 * i) * HW;
        *(float4*)(qn + off) = xv[i];
        *(uint2*)(qb + off)  = make_uint2(pack_hi(xv[i].x, xv[i].y), pack_hi(xv[i].z, xv[i].w));
        float4 s4 = *(const float4*)(s0 + off);
        Sacc.x += s4.x * xv[i].x; Sacc.y += s4.y * xv[i].y;
        Sacc.z += s4.z * xv[i].z; Sacc.w += s4.w * xv[i].w;
        nacc += xv[i].x * xv[i].x + xv[i].y * xv[i].y
              + xv[i].z * xv[i].z + xv[i].w * xv[i].w;
    }
    Sred[cg][pq] = Sacc;
    nacc = warpReduce(nacc);
    if (lane == 0) nsh[wid] = nacc;
    __syncthreads();
    if (t < 8) {
        float4 s = make_float4(0.f, 0.f, 0.f, 0.f);
        #pragma unroll
        for (int g2 = 0; g2 < 32; g2++) {
            float4 a = Sred[g2][t];
            s.x += a.x; s.y += a.y; s.z += a.z; s.w += a.w;
        }
        Ssm[t] = s;
    }
    if (t == 8) {
        float s = 0.f;
        #pragma unroll
        for (int w2 = 0; w2 < 8; w2++) s += nsh[w2];
        g_npart[b][blockIdx.x] = s;
    }
    __syncthreads();
    float4 S4 = Ssm[pq];
    #pragma unroll
    for (int i = 0; i < 8; i++) {
        size_t off = base + (size_t)(cg + 32 * i) * HW;
        float4 s4 = *(const float4*)(s0 + off);          // L2-hot re-read
        float rx = s4.x * (xv[i].x - S4.x), ry = s4.y * (xv[i].y - S4.y);
        float rz = s4.z * (xv[i].z - S4.z), rw = s4.w * (xv[i].w - S4.w);
        *(uint2*)(g_Rhi + off) = make_uint2(pack_hi(rx, ry), pack_hi(rz, rw));
        *(uint2*)(g_Rlo + off) = make_uint2(pack_lo(rx, ry), pack_lo(rz, rw));
    }
}

// ---------------- fused GEMM + dots (2-stage pipeline, bf16 dot reads, inline norm finalize) ----------------
static __device__ __forceinline__ void cp_tileA(uint32_t dstbase, const __nv_bfloat16* src,
                                                int kc, int tid) {
    #pragma unroll
    for (int i = 0; i < 2; i++) {
        int x   = tid + (i << 8);     // 0..511 16B chunks
        int row = x >> 2;             // 0..127
        int cb  = (x & 3) << 4;       // 0,16,32,48
        const char* gp = (const char*)(src + (size_t)row * 256 + kc) + cb;
        uint32_t dp = dstbase + (uint32_t)(row * 64 + (cb ^ (((row >> 1) & 3) << 4)));
        CP16(dp, gp);
    }
}
static __device__ __forceinline__ void cp_tileB(uint32_t dstbase, const __nv_bfloat16* srcb,
                                                int kc, int tid) {
    #pragma unroll
    for (int i = 0; i < 2; i++) {
        int x   = tid + (i << 8);     // 0..511
        int row = x >> 4;             // 0..31 (c within chunk)
        int cb  = (x & 15) << 4;      // byte col 0..240
        const char* gp = (const char*)(srcb + (size_t)(kc + row) * HW) + cb;
        CP16(dstbase + (uint32_t)(row * 272 + cb), gp);
    }
}

#define STG_SZ 33792   // per-stage: AH 8192 + AL 8192 + BH 8704 + BL 8704

__global__ void __launch_bounds__(256, 2) k_gemm_fused(const float* __restrict__ v,
                                                       int kstep, int write_w, int b0) {
    extern __shared__ __align__(128) char smem[];
    const int tid  = threadIdx.x;
    const int wid  = tid >> 5;
    const int lane = tid & 31;
    const int g    = lane >> 2;
    const int q    = lane & 3;
    const int l8   = lane & 7;
    const int g8   = lane >> 3;
    const int wm   = wid >> 2;       // 0..1
    const int wn   = wid & 3;        // 0..3
    const int p0   = blockIdx.x * 128;
    const int mt   = blockIdx.y;
    const int b    = b0 + blockIdx.z;

    uint32_t sb = smem_u32(smem);

    const __nv_bfloat16* Whi = g_Whi + (size_t)mt * 128 * 256;
    const __nv_bfloat16* Wlo = g_Wlo + (size_t)mt * 128 * 256;
    const __nv_bfloat16* RhiB = g_Rhi + (size_t)b * PER_B + p0;
    const __nv_bfloat16* RloB = g_Rlo + (size_t)b * PER_B + p0;
    const size_t qtile = (size_t)b * PER_B + (size_t)(mt * 128) * HW + p0;

    // prologue: chunk 0 into stage 0
    cp_tileA(sb,         Whi,  0, tid);
    cp_tileA(sb + 8192,  Wlo,  0, tid);
    cp_tileB(sb + 16384, RhiB, 0, tid);
    cp_tileB(sb + 25088, RloB, 0, tid);
    CP_COMMIT();

    // inline norm finalize -> inv_k (overlaps chunk-0 load); 128 partials
    __shared__ float invsh;
    __shared__ float rsh[4];
    if (tid < 128) {
        float val = warpReduce(g_npart[b][tid]);
        if (lane == 0) rsh[wid] = val;
    }
    __syncthreads();
    if (tid == 0) {
        float hn = sqrtf(rsh[0] + rsh[1] + rsh[2] + rsh[3]);
        float iv = (kstep == 0) ? (1.f / hn) : (1.f / (hn + EPSF));
        invsh = iv;
        if (blockIdx.x == 0 && blockIdx.y == 0) {
            g_inv[kstep][b] = iv;
            if (kstep == 0) g_vnorm[b] = hn;
            else            g_H[b][kstep][kstep - 1] = hn;
        }
    }

    float acc[4][4][4];
    #pragma unroll
    for (int i = 0; i < 4; i++)
        #pragma unroll
        for (int j = 0; j < 4; j++)
            #pragma unroll
            for (int e = 0; e < 4; e++) acc[i][j][e] = 0.f;

    const uint32_t aR0 = (uint32_t)(wm * 64 + (g8 & 1) * 8 + l8);
    const uint32_t aK  = (uint32_t)(g8 >> 1) << 4;
    const uint32_t bRow = (uint32_t)(((lane >> 3) & 1) * 8 + l8);
    const uint32_t bCol = (uint32_t)(wn * 64) + ((uint32_t)(lane >> 4)) * 16;

    #pragma unroll
    for (int ci = 0; ci < 8; ci++) {
        CP_WAIT0();
        __syncthreads();
        if (ci < 7) {
            uint32_t st = sb + (uint32_t)(((ci + 1) & 1) * STG_SZ);
            int kc = (ci + 1) * 32;
            cp_tileA(st,         Whi,  kc, tid);
            cp_tileA(st + 8192,  Wlo,  kc, tid);
            cp_tileB(st + 16384, RhiB, kc, tid);
            cp_tileB(st + 25088, RloB, kc, tid);
            CP_COMMIT();
        }
        const uint32_t ST = sb + (uint32_t)((ci & 1) * STG_SZ);
        const uint32_t AHs = ST, ALs = ST + 8192, BHs = ST + 16384, BLs = ST + 25088;

        #pragma unroll
        for (int kf = 0; kf < 2; kf++) {
            const uint32_t cbA = (uint32_t)(kf * 32) + aK;
            uint32_t ah[4][4], al[4][4], bh[4][2], bl[4][2];
            #pragma unroll
            for (int mf = 0; mf < 4; mf++) {
                uint32_t r  = aR0 + (uint32_t)(mf * 16);
                uint32_t ao = r * 64 + (cbA ^ (((r >> 1) & 3) << 4));
                LDSM4(ah[mf][0], ah[mf][1], ah[mf][2], ah[mf][3], AHs + ao);
                LDSM4(al[mf][0], al[mf][1], al[mf][2], al[mf][3], ALs + ao);
            }
            #pragma unroll
            for (int j2 = 0; j2 < 2; j2++) {
                uint32_t bo = (uint32_t)(kf * 16 + bRow) * 272 + bCol + (uint32_t)(j2 * 32);
                LDSM4T(bh[2*j2][0], bh[2*j2][1], bh[2*j2+1][0], bh[2*j2+1][1], BHs + bo);
                LDSM4T(bl[2*j2][0], bl[2*j2][1], bl[2*j2+1][0], bl[2*j2+1][1], BLs + bo);
            }
            #pragma unroll
            for (int mf = 0; mf < 4; mf++)
                #pragma unroll
                for (int nf = 0; nf < 4; nf++) {
                    mma_bf16(acc[mf][nf], ah[mf], bh[nf]);   // Whi*Rhi
                    mma_bf16(acc[mf][nf], al[mf], bh[nf]);   // Wlo*Rhi
                    mma_bf16(acc[mf][nf], ah[mf], bl[nf]);   // Whi*Rlo
                }
        }
    }

    // scale by inv_k (deferred normalization of q_k)
    const float inv = invsh;
    #pragma unroll
    for (int mf = 0; mf < 4; mf++)
        #pragma unroll
        for (int nf = 0; nf < 4; nf++)
            #pragma unroll
            for (int e = 0; e < 4; e++) acc[mf][nf][e] *= inv;

    if (write_w) {
        float* dst = g_w + qtile;
        #pragma unroll
        for (int mf = 0; mf < 4; mf++) {
            int m = wm * 64 + mf * 16 + g;
            #pragma unroll
            for (int nf = 0; nf < 4; nf++) {
                int pp = wn * 32 + nf * 8 + q * 2;
                *(float2*)(dst + (size_t)m * HW + pp)       = make_float2(acc[mf][nf][0], acc[mf][nf][1]);
                *(float2*)(dst + (size_t)(m + 8) * HW + pp) = make_float2(acc[mf][nf][2], acc[mf][nf][3]);
            }
        }
    }

    // fused dots vs bf16 Q mirror: raw partial <Qbf_j, w> over this CTA's 128x128 tile
    __shared__ float dsh[8][8];
    for (int j = 0; j <= kstep; j++) {
        const __nv_bfloat16* Qb = g_Qbf[j] + qtile;
        float d = 0.f;
        #pragma unroll
        for (int mf = 0; mf < 4; mf++) {
            int m = wm * 64 + mf * 16 + g;
            #pragma unroll
            for (int nf = 0; nf < 4; nf++) {
                int pp = wn * 32 + nf * 8 + q * 2;
                float2 a0 = __bfloat1622float2(*(const __nv_bfloat162*)(Qb + (size_t)m * HW + pp));
                float2 a1 = __bfloat1622float2(*(const __nv_bfloat162*)(Qb + (size_t)(m + 8) * HW + pp));
                d += acc[mf][nf][0] * a0.x + acc[mf][nf][1] * a0.y
                   + acc[mf][nf][2] * a1.x + acc[mf][nf][3] * a1.y;
            }
        }
        d = warpReduce(d);
        if (lane == 0) dsh[j][wid] = d;
    }
    __syncthreads();
    if (tid < 64) {
        int j = tid >> 3, w8 = tid & 7;
        float val = (j <= kstep) ? dsh[j][w8] : 0.f;
        #pragma unroll
        for (int off = 4; off > 0; off >>= 1) val += __shfl_xor_sync(0xFFFFFFFFu, val, off);
        if (w8 == 0 && j <= kstep) g_dpart[j][b][mt * 32 + blockIdx.x] = val;
    }
}

// ---------------- expm of 9x9 (scaling-squaring + Taylor, fp64) + H col 7 finalize ----------------
__global__ void k_expm(int b0) {
    const int b = b0 + blockIdx.x;
    const int t = threadIdx.x;
    __shared__ double A[81], M[81], P[81], Pn[81];
    __shared__ float Hc7[8];
    __shared__ int ssc;

    if (t < 8) {
        float dv = 0.f;
        for (int i2 = 0; i2 < 64; i2++) dv += g_dpart[t][b][i2];
        Hc7[t] = dv * g_inv[t][b];
    }
    __syncthreads();

    if (t < 81) {
        int i = t / 9, j = t % 9;
        double e = 0.0;
        if (i < 8 && j < 8) e = (j == 7) ? (double)Hc7[i] : (double)g_H[b][i][j];
        if (i == 0 && j == 8) e = 1.0;
        A[t] = e;
    }
    __syncthreads();
    if (t == 0) {
        double nrm = 0.0;
        for (int i = 0; i < 9; i++) {
            double rs = 0.0;
            for (int j = 0; j < 9; j++) rs += fabs(A[i * 9 + j]);
            if (rs > nrm) nrm = rs;
        }
        int s = 0;
        while (nrm > 0.5 && s < 60) { nrm *= 0.5; s++; }
        ssc = s;
    }
    __syncthreads();
    const int s = ssc;
    if (t < 81) {
        A[t] = ldexp(A[t], -s);
        M[t] = ((t % 10 == 0) ? 1.0 : 0.0) + A[t];
        P[t] = A[t];
    }
    __syncthreads();
    for (int it = 2; it <= 22; it++) {
        if (t < 81) {
            int i = t / 9, j = t % 9;
            double acc = 0.0;
            #pragma unroll
            for (int kk = 0; kk < 9; kk++) acc += P[i * 9 + kk] * A[kk * 9 + j];
            Pn[t] = acc / (double)it;
        }
        __syncthreads();
        if (t < 81) { P[t] = Pn[t]; M[t] += P[t]; }
        __syncthreads();
    }
    for (int qq = 0; qq < s; qq++) {
        if (t < 81) {
            int i = t / 9, j = t % 9;
            double acc = 0.0;
            #pragma unroll
            for (int kk = 0; kk < 9; kk++) acc += M[i * 9 + kk] * M[kk * 9 + j];
            Pn[t] = acc;
        }
        __syncthreads();
        if (t < 81) M[t] = Pn[t];
        __syncthreads();
    }
    if (t < 8) {
        double coord = M[t * 9 + 8];
        g_cf[b][t] = (float)(coord * (double)g_vnorm[b] * (double)g_inv[t][b]);
    }
}

// ---------------- final combine (float4, fp32 Q) ----------------
__global__ void __launch_bounds__(256) k_combine(const float* __restrict__ v,
                                                 float* __restrict__ out) {
    int b = blockIdx.y;
    size_t idx = (size_t)b * PER_B + ((size_t)blockIdx.x * 256 + threadIdx.x) * 4;
    float cf[8];
    #pragma unroll
    for (int j = 0; j < 8; j++) cf[j] = g_cf[b][j];
    float4 x = make_float4(0.f, 0.f, 0.f, 0.f);
    #pragma unroll
    for (int j = 0; j < 8; j++) {
        const float* qs = (j == 0) ? v : g_Q[j - 1];
        float4 q = *(const float4*)(qs + idx);
        x.x += cf[j] * q.x; x.y += cf[j] * q.y;
        x.z += cf[j] * q.z; x.w += cf[j] * q.w;
    }
    *(float4*)(out + idx) = x;
}

// ---------------- driver: 4 streams x 2 batches, fork/join via events ----------------
extern "C" void kernel_launch(void* const* d_in, const int* in_sizes, int n_in,
                              void* d_out, int out_size) {
    const float* s0 = (const float*)d_in[0];
    const float* v  = (const float*)d_in[1];
    const float* Wm = (const float*)d_in[2];
    float* out = (float*)d_out;

    const int GEMM_SMEM = 2 * STG_SZ;   // 67584
    cudaFuncSetAttribute(k_gemm_fused, cudaFuncAttributeMaxDynamicSharedMemorySize, GEMM_SMEM);

    dim3 gP(HW / 32, 2);             // per-pair: 128 p-tiles x 2 batches
    dim3 gGemm(HW / 128, 2, 2);      // per-pair: 32 p-tiles x 2 m-tiles x 2 batches
    dim3 gComb(PER_B / 1024, Bb);

    k_splitW<<<Cc * Cc / 256, 256>>>(Wm);
    cudaEventRecord(g_si.root, 0);

    for (int s = 0; s < 4; s++) {
        cudaStream_t st = g_si.st[s];
        const int b0 = s * 2;
        cudaStreamWaitEvent(st, g_si.root, 0);
        k_repl0<<<gP, 256, 0, st>>>(s0, v, b0);
        for (int k = 0; k < 8; k++) {
            k_gemm_fused<<<gGemm, 256, GEMM_SMEM, st>>>(v, k, (k < 7) ? 1 : 0, b0);
            if (k < 7) k_upd_repl<<<gP, 256, 0, st>>>(s0, v, k, b0);
        }
        k_expm<<<2, 128, 0, st>>>(b0);
        cudaEventRecord(g_si.join[s], st);
    }

    for (int s = 0; s < 4; s++) cudaStreamWaitEvent(0, g_si.join[s], 0);
    k_combine<<<gComb, 256>>>(v, out);
}

// round 13
// speedup vs baseline: 1.2905x; 1.0416x over previous
#include <cuda_runtime.h>
#include <cuda_bf16.h>
#include <math.h>
#include <stdint.h>

#define Bb    8
#define Cc    256
#define HW    4096
#define PER_B (Cc * HW)          // 2^20
#define EPSF  1e-12f

// ---------------- device scratch ----------------
__device__ float g_Q[7][Bb * PER_B];   // unnormalized Krylov vectors fp32, slots 1..7 (slot 0 = input v)
__device__ __nv_bfloat16 g_Qbf[8][Bb * PER_B]; // bf16 mirror of Qu_j (slot 0 = bf16(v)) for dots
__device__ float g_w[Bb * PER_B];      // GEMM output (scaled by inv_k)
__device__ __nv_bfloat16 g_Rhi[Bb * PER_B];  // replicator out, layout [b][c][p] (p contiguous), hi
__device__ __nv_bfloat16 g_Rlo[Bb * PER_B];  // lo residual
__device__ __nv_bfloat16 g_Whi[Cc * Cc];
__device__ __nv_bfloat16 g_Wlo[Cc * Cc];
__device__ float g_dpart[8][Bb][64];   // raw dot partials [j][b][mt*32+pblock]
__device__ float g_npart[Bb][128];     // norm partials
__device__ float g_H[Bb][8][8];
__device__ float g_inv[8][Bb];
__device__ float g_vnorm[Bb];
__device__ float g_cf[Bb][8];

// ---------------- stream/event infra (created once at load; no device memory) ----------------
namespace {
struct StreamInit {
    cudaStream_t st[8];
    cudaEvent_t  root;
    cudaEvent_t  join[8];
    StreamInit() {
        for (int i = 0; i < 8; i++) cudaStreamCreateWithFlags(&st[i], cudaStreamNonBlocking);
        cudaEventCreateWithFlags(&root, cudaEventDisableTiming);
        for (int i = 0; i < 8; i++) cudaEventCreateWithFlags(&join[i], cudaEventDisableTiming);
    }
};
StreamInit g_si;
}

// ---------------- PTX helpers ----------------
static __device__ __forceinline__ uint32_t smem_u32(const void* p) {
    uint32_t a;
    asm("{ .reg .u64 t; cvta.to.shared.u64 t, %1; cvt.u32.u64 %0, t; }" : "=r"(a) : "l"(p));
    return a;
}
#define CP16(dst, src) \
    asm volatile("cp.async.cg.shared.global [%0], [%1], 16;" :: "r"(dst), "l"(src))
#define CP_COMMIT() asm volatile("cp.async.commit_group;" ::: "memory")
#define CP_WAIT0()  asm volatile("cp.async.wait_group 0;" ::: "memory")
#define LDSM4(r0, r1, r2, r3, addr) \
    asm volatile("ldmatrix.sync.aligned.m8n8.x4.shared.b16 {%0,%1,%2,%3}, [%4];" \
        : "=r"(r0), "=r"(r1), "=r"(r2), "=r"(r3) : "r"(addr))
#define LDSM4T(r0, r1, r2, r3, addr) \
    asm volatile("ldmatrix.sync.aligned.m8n8.x4.trans.shared.b16 {%0,%1,%2,%3}, [%4];" \
        : "=r"(r0), "=r"(r1), "=r"(r2), "=r"(r3) : "r"(addr))

static __device__ __forceinline__ void mma_bf16(float* c, const uint32_t* a, const uint32_t* b) {
    asm volatile("mma.sync.aligned.m16n8k16.row.col.f32.bf16.bf16.f32 "
        "{%0,%1,%2,%3}, {%4,%5,%6,%7}, {%8,%9}, {%0,%1,%2,%3};"
        : "+f"(c[0]), "+f"(c[1]), "+f"(c[2]), "+f"(c[3])
        : "r"(a[0]), "r"(a[1]), "r"(a[2]), "r"(a[3]), "r"(b[0]), "r"(b[1]));
}

static __device__ __forceinline__ float warpReduce(float v) {
    #pragma unroll
    for (int off = 16; off > 0; off >>= 1) v += __shfl_xor_sync(0xFFFFFFFFu, v, off);
    return v;
}

static __device__ __forceinline__ uint32_t pack_hi(float a, float b) {
    __nv_bfloat16 ha = __float2bfloat16(a), hb = __float2bfloat16(b);
    return (uint32_t)__bfloat16_as_ushort(ha) | ((uint32_t)__bfloat16_as_ushort(hb) << 16);
}
static __device__ __forceinline__ uint32_t pack_lo(float a, float b) {
    __nv_bfloat16 ha = __float2bfloat16(a), hb = __float2bfloat16(b);
    float la = a - __bfloat162float(ha), lb = b - __bfloat162float(hb);
    __nv_bfloat16 pa = __float2bfloat16(la), pb = __float2bfloat16(lb);
    return (uint32_t)__bfloat16_as_ushort(pa) | ((uint32_t)__bfloat16_as_ushort(pb) << 16);
}

// ---------------- W split to bf16 hi/lo ----------------
__global__ void __launch_bounds__(256) k_splitW(const float* __restrict__ Wm) {
    int i = blockIdx.x * 256 + threadIdx.x;
    float x = Wm[i];
    __nv_bfloat16 h = __float2bfloat16(x);
    g_Whi[i] = h;
    g_Wlo[i] = __float2bfloat16(x - __bfloat162float(h));
}

// ---------------- step-0 replicator: R(v) + Qbf0 + ||v||^2 partials (32p x 256c, 256 thr) ----------------
__global__ void __launch_bounds__(256, 2) k_repl0(const float* __restrict__ s0,
                                                  const float* __restrict__ v, int b) {
    const int t = threadIdx.x, lane = t & 31, wid = t >> 5;
    const int pq = t & 7;           // p-quad (8 quads = 32 p)
    const int cg = t >> 3;          // 0..31 c-groups
    const int p0 = blockIdx.x * 32;
    const size_t base = (size_t)b * PER_B + p0 + pq * 4;

    __shared__ float4 Sred[32][8];
    __shared__ float4 Ssm[8];
    __shared__ float  nsh[8];

    float4 xv[8];
    float4 Sacc = make_float4(0.f, 0.f, 0.f, 0.f);
    float nacc = 0.f;
    #pragma unroll
    for (int i = 0; i < 8; i++) {
        size_t off = base + (size_t)(cg + 32 * i) * HW;
        float4 x4 = *(const float4*)(v + off);
        float4 s4 = *(const float4*)(s0 + off);
        xv[i] = x4;
        Sacc.x += s4.x * x4.x; Sacc.y += s4.y * x4.y;
        Sacc.z += s4.z * x4.z; Sacc.w += s4.w * x4.w;
        nacc += x4.x * x4.x + x4.y * x4.y + x4.z * x4.z + x4.w * x4.w;
    }
    Sred[cg][pq] = Sacc;
    nacc = warpReduce(nacc);
    if (lane == 0) nsh[wid] = nacc;
    __syncthreads();
    if (t < 8) {
        float4 s = make_float4(0.f, 0.f, 0.f, 0.f);
        #pragma unroll
        for (int g2 = 0; g2 < 32; g2++) {
            float4 a = Sred[g2][t];
            s.x += a.x; s.y += a.y; s.z += a.z; s.w += a.w;
        }
        Ssm[t] = s;
    }
    if (t == 8) {
        float s = 0.f;
        #pragma unroll
        for (int w2 = 0; w2 < 8; w2++) s += nsh[w2];
        g_npart[b][blockIdx.x] = s;
    }
    __syncthreads();
    float4 S4 = Ssm[pq];
    #pragma unroll
    for (int i = 0; i < 8; i++) {
        size_t off = base + (size_t)(cg + 32 * i) * HW;
        float4 s4 = *(const float4*)(s0 + off);          // L2-hot
        float rx = s4.x * (xv[i].x - S4.x), ry = s4.y * (xv[i].y - S4.y);
        float rz = s4.z * (xv[i].z - S4.z), rw = s4.w * (xv[i].w - S4.w);
        *(uint2*)(g_Rhi + off)    = make_uint2(pack_hi(rx, ry), pack_hi(rz, rw));
        *(uint2*)(g_Rlo + off)    = make_uint2(pack_lo(rx, ry), pack_lo(rz, rw));
        *(uint2*)(g_Qbf[0] + off) = make_uint2(pack_hi(xv[i].x, xv[i].y), pack_hi(xv[i].z, xv[i].w));
    }
}

// ---------------- fused update + replicator + dots_fin + norm (k = 0..6) ----------------
__global__ void __launch_bounds__(256, 2) k_upd_repl(const float* __restrict__ s0,
                                                     const float* __restrict__ v, int k, int b) {
    const int t = threadIdx.x, lane = t & 31, wid = t >> 5;
    const int pq = t & 7;
    const int cg = t >> 3;
    const int p0 = blockIdx.x * 32;
    const size_t base = (size_t)b * PER_B + p0 + pq * 4;

    __shared__ float  hc[8];
    __shared__ float4 Sred[32][8];
    __shared__ float4 Ssm[8];
    __shared__ float  nsh[8];

    // inline dots finalize: warp j (j<=k<=6, 8 warps) reduces 64 partials -> hcoef
    if (wid <= k) {
        float dv = g_dpart[wid][b][lane] + g_dpart[wid][b][lane + 32];
        dv = warpReduce(dv);
        if (lane == 0) {
            float invj = g_inv[wid][b];
            float h = dv * invj;
            hc[wid] = h * invj;
            if (blockIdx.x == 0) g_H[b][wid][k] = h;
        }
    }
    __syncthreads();

    float4 xv[8];
    #pragma unroll
    for (int i = 0; i < 8; i++) {
        size_t off = base + (size_t)(cg + 32 * i) * HW;
        xv[i] = *(const float4*)(g_w + off);
    }
    for (int j = 0; j <= k; j++) {
        const float* __restrict__ Qj = (j == 0) ? v : g_Q[j - 1];
        float cf = hc[j];
        #pragma unroll
        for (int i = 0; i < 8; i++) {
            size_t off = base + (size_t)(cg + 32 * i) * HW;
            float4 q = *(const float4*)(Qj + off);
            xv[i].x -= cf * q.x; xv[i].y -= cf * q.y;
            xv[i].z -= cf * q.z; xv[i].w -= cf * q.w;
        }
    }

    float* __restrict__ qn = g_Q[k];
    __nv_bfloat16* __restrict__ qb = g_Qbf[k + 1];
    float4 Sacc = make_float4(0.f, 0.f, 0.f, 0.f);
    float nacc = 0.f;
    #pragma unroll
    for (int i = 0; i < 8; i++) {
        size_t off = base + (size_t)(cg + 32 * i) * HW;
        *(float4*)(qn + off) = xv[i];
        *(uint2*)(qb + off)  = make_uint2(pack_hi(xv[i].x, xv[i].y), pack_hi(xv[i].z, xv[i].w));
        float4 s4 = *(const float4*)(s0 + off);
        Sacc.x += s4.x * xv[i].x; Sacc.y += s4.y * xv[i].y;
        Sacc.z += s4.z * xv[i].z; Sacc.w += s4.w * xv[i].w;
        nacc += xv[i].x * xv[i].x + xv[i].y * xv[i].y
              + xv[i].z * xv[i].z + xv[i].w * xv[i].w;
    }
    Sred[cg][pq] = Sacc;
    nacc = warpReduce(nacc);
    if (lane == 0) nsh[wid] = nacc;
    __syncthreads();
    if (t < 8) {
        float4 s = make_float4(0.f, 0.f, 0.f, 0.f);
        #pragma unroll
        for (int g2 = 0; g2 < 32; g2++) {
            float4 a = Sred[g2][t];
            s.x += a.x; s.y += a.y; s.z += a.z; s.w += a.w;
        }
        Ssm[t] = s;
    }
    if (t == 8) {
        float s = 0.f;
        #pragma unroll
        for (int w2 = 0; w2 < 8; w2++) s += nsh[w2];
        g_npart[b][blockIdx.x] = s;
    }
    __syncthreads();
    float4 S4 = Ssm[pq];
    #pragma unroll
    for (int i = 0; i < 8; i++) {
        size_t off = base + (size_t)(cg + 32 * i) * HW;
        float4 s4 = *(const float4*)(s0 + off);          // L2-hot re-read
        float rx = s4.x * (xv[i].x - S4.x), ry = s4.y * (xv[i].y - S4.y);
        float rz = s4.z * (xv[i].z - S4.z), rw = s4.w * (xv[i].w - S4.w);
        *(uint2*)(g_Rhi + off) = make_uint2(pack_hi(rx, ry), pack_hi(rz, rw));
        *(uint2*)(g_Rlo + off) = make_uint2(pack_lo(rx, ry), pack_lo(rz, rw));
    }
}

// ---------------- fused GEMM + dots (2-stage pipeline, bf16 dot reads, inline norm finalize) ----------------
static __device__ __forceinline__ void cp_tileA(uint32_t dstbase, const __nv_bfloat16* src,
                                                int kc, int tid) {
    #pragma unroll
    for (int i = 0; i < 2; i++) {
        int x   = tid + (i << 8);     // 0..511 16B chunks
        int row = x >> 2;             // 0..127
        int cb  = (x & 3) << 4;       // 0,16,32,48
        const char* gp = (const char*)(src + (size_t)row * 256 + kc) + cb;
        uint32_t dp = dstbase + (uint32_t)(row * 64 + (cb ^ (((row >> 1) & 3) << 4)));
        CP16(dp, gp);
    }
}
static __device__ __forceinline__ void cp_tileB(uint32_t dstbase, const __nv_bfloat16* srcb,
                                                int kc, int tid) {
    #pragma unroll
    for (int i = 0; i < 2; i++) {
        int x   = tid + (i << 8);     // 0..511
        int row = x >> 4;             // 0..31 (c within chunk)
        int cb  = (x & 15) << 4;      // byte col 0..240
        const char* gp = (const char*)(srcb + (size_t)(kc + row) * HW) + cb;
        CP16(dstbase + (uint32_t)(row * 272 + cb), gp);
    }
}

#define STG_SZ 33792   // per-stage: AH 8192 + AL 8192 + BH 8704 + BL 8704

__global__ void __launch_bounds__(256, 2) k_gemm_fused(const float* __restrict__ v,
                                                       int kstep, int write_w, int b) {
    extern __shared__ __align__(128) char smem[];
    const int tid  = threadIdx.x;
    const int wid  = tid >> 5;
    const int lane = tid & 31;
    const int g    = lane >> 2;
    const int q    = lane & 3;
    const int l8   = lane & 7;
    const int g8   = lane >> 3;
    const int wm   = wid >> 2;       // 0..1
    const int wn   = wid & 3;        // 0..3
    const int p0   = blockIdx.x * 128;
    const int mt   = blockIdx.y;

    uint32_t sb = smem_u32(smem);

    const __nv_bfloat16* Whi = g_Whi + (size_t)mt * 128 * 256;
    const __nv_bfloat16* Wlo = g_Wlo + (size_t)mt * 128 * 256;
    const __nv_bfloat16* RhiB = g_Rhi + (size_t)b * PER_B + p0;
    const __nv_bfloat16* RloB = g_Rlo + (size_t)b * PER_B + p0;
    const size_t qtile = (size_t)b * PER_B + (size_t)(mt * 128) * HW + p0;

    // prologue: chunk 0 into stage 0
    cp_tileA(sb,         Whi,  0, tid);
    cp_tileA(sb + 8192,  Wlo,  0, tid);
    cp_tileB(sb + 16384, RhiB, 0, tid);
    cp_tileB(sb + 25088, RloB, 0, tid);
    CP_COMMIT();

    // inline norm finalize -> inv_k (overlaps chunk-0 load); 128 partials
    __shared__ float invsh;
    __shared__ float rsh[4];
    if (tid < 128) {
        float val = warpReduce(g_npart[b][tid]);
        if (lane == 0) rsh[wid] = val;
    }
    __syncthreads();
    if (tid == 0) {
        float hn = sqrtf(rsh[0] + rsh[1] + rsh[2] + rsh[3]);
        float iv = (kstep == 0) ? (1.f / hn) : (1.f / (hn + EPSF));
        invsh = iv;
        if (blockIdx.x == 0 && blockIdx.y == 0) {
            g_inv[kstep][b] = iv;
            if (kstep == 0) g_vnorm[b] = hn;
            else            g_H[b][kstep][kstep - 1] = hn;
        }
    }

    float acc[4][4][4];
    #pragma unroll
    for (int i = 0; i < 4; i++)
        #pragma unroll
        for (int j = 0; j < 4; j++)
            #pragma unroll
            for (int e = 0; e < 4; e++) acc[i][j][e] = 0.f;

    const uint32_t aR0 = (uint32_t)(wm * 64 + (g8 & 1) * 8 + l8);
    const uint32_t aK  = (uint32_t)(g8 >> 1) << 4;
    const uint32_t bRow = (uint32_t)(((lane >> 3) & 1) * 8 + l8);
    const uint32_t bCol = (uint32_t)(wn * 64) + ((uint32_t)(lane >> 4)) * 16;

    #pragma unroll
    for (int ci = 0; ci < 8; ci++) {
        CP_WAIT0();
        __syncthreads();
        if (ci < 7) {
            uint32_t st = sb + (uint32_t)(((ci + 1) & 1) * STG_SZ);
            int kc = (ci + 1) * 32;
            cp_tileA(st,         Whi,  kc, tid);
            cp_tileA(st + 8192,  Wlo,  kc, tid);
            cp_tileB(st + 16384, RhiB, kc, tid);
            cp_tileB(st + 25088, RloB, kc, tid);
            CP_COMMIT();
        }
        const uint32_t ST = sb + (uint32_t)((ci & 1) * STG_SZ);
        const uint32_t AHs = ST, ALs = ST + 8192, BHs = ST + 16384, BLs = ST + 25088;

        #pragma unroll
        for (int kf = 0; kf < 2; kf++) {
            const uint32_t cbA = (uint32_t)(kf * 32) + aK;
            uint32_t ah[4][4], al[4][4], bh[4][2], bl[4][2];
            #pragma unroll
            for (int mf = 0; mf < 4; mf++) {
                uint32_t r  = aR0 + (uint32_t)(mf * 16);
                uint32_t ao = r * 64 + (cbA ^ (((r >> 1) & 3) << 4));
                LDSM4(ah[mf][0], ah[mf][1], ah[mf][2], ah[mf][3], AHs + ao);
                LDSM4(al[mf][0], al[mf][1], al[mf][2], al[mf][3], ALs + ao);
            }
            #pragma unroll
            for (int j2 = 0; j2 < 2; j2++) {
                uint32_t bo = (uint32_t)(kf * 16 + bRow) * 272 + bCol + (uint32_t)(j2 * 32);
                LDSM4T(bh[2*j2][0], bh[2*j2][1], bh[2*j2+1][0], bh[2*j2+1][1], BHs + bo);
                LDSM4T(bl[2*j2][0], bl[2*j2][1], bl[2*j2+1][0], bl[2*j2+1][1], BLs + bo);
            }
            #pragma unroll
            for (int mf = 0; mf < 4; mf++)
                #pragma unroll
                for (int nf = 0; nf < 4; nf++) {
                    mma_bf16(acc[mf][nf], ah[mf], bh[nf]);   // Whi*Rhi
                    mma_bf16(acc[mf][nf], al[mf], bh[nf]);   // Wlo*Rhi
                    mma_bf16(acc[mf][nf], ah[mf], bl[nf]);   // Whi*Rlo
                }
        }
    }

    // scale by inv_k (deferred normalization of q_k)
    const float inv = invsh;
    #pragma unroll
    for (int mf = 0; mf < 4; mf++)
        #pragma unroll
        for (int nf = 0; nf < 4; nf++)
            #pragma unroll
            for (int e = 0; e < 4; e++) acc[mf][nf][e] *= inv;

    if (write_w) {
        float* dst = g_w + qtile;
        #pragma unroll
        for (int mf = 0; mf < 4; mf++) {
            int m = wm * 64 + mf * 16 + g;
            #pragma unroll
            for (int nf = 0; nf < 4; nf++) {
                int pp = wn * 32 + nf * 8 + q * 2;
                *(float2*)(dst + (size_t)m * HW + pp)       = make_float2(acc[mf][nf][0], acc[mf][nf][1]);
                *(float2*)(dst + (size_t)(m + 8) * HW + pp) = make_float2(acc[mf][nf][2], acc[mf][nf][3]);
            }
        }
    }

    // fused dots vs bf16 Q mirror: raw partial <Qbf_j, w> over this CTA's 128x128 tile
    __shared__ float dsh[8][8];
    for (int j = 0; j <= kstep; j++) {
        const __nv_bfloat16* Qb = g_Qbf[j] + qtile;
        float d = 0.f;
        #pragma unroll
        for (int mf = 0; mf < 4; mf++) {
            int m = wm * 64 + mf * 16 + g;
            #pragma unroll
            for (int nf = 0; nf < 4; nf++) {
                int pp = wn * 32 + nf * 8 + q * 2;
                float2 a0 = __bfloat1622float2(*(const __nv_bfloat162*)(Qb + (size_t)m * HW + pp));
                float2 a1 = __bfloat1622float2(*(const __nv_bfloat162*)(Qb + (size_t)(m + 8) * HW + pp));
                d += acc[mf][nf][0] * a0.x + acc[mf][nf][1] * a0.y
                   + acc[mf][nf][2] * a1.x + acc[mf][nf][3] * a1.y;
            }
        }
        d = warpReduce(d);
        if (lane == 0) dsh[j][wid] = d;
    }
    __syncthreads();
    if (tid < 64) {
        int j = tid >> 3, w8 = tid & 7;
        float val = (j <= kstep) ? dsh[j][w8] : 0.f;
        #pragma unroll
        for (int off = 4; off > 0; off >>= 1) val += __shfl_xor_sync(0xFFFFFFFFu, val, off);
        if (w8 == 0 && j <= kstep) g_dpart[j][b][mt * 32 + blockIdx.x] = val;
    }
}

// ---------------- expm of 9x9 (scaling-squaring + Taylor, fp64) + H col 7 finalize ----------------
__global__ void k_expm(int b) {
    const int t = threadIdx.x;
    __shared__ double A[81], M[81], P[81], Pn[81];
    __shared__ float Hc7[8];
    __shared__ int ssc;

    if (t < 8) {
        float dv = 0.f;
        for (int i2 = 0; i2 < 64; i2++) dv += g_dpart[t][b][i2];
        Hc7[t] = dv * g_inv[t][b];
    }
    __syncthreads();

    if (t < 81) {
        int i = t / 9, j = t % 9;
        double e = 0.0;
        if (i < 8 && j < 8) e = (j == 7) ? (double)Hc7[i] : (double)g_H[b][i][j];
        if (i == 0 && j == 8) e = 1.0;
        A[t] = e;
    }
    __syncthreads();
    if (t == 0) {
        double nrm = 0.0;
        for (int i = 0; i < 9; i++) {
            double rs = 0.0;
            for (int j = 0; j < 9; j++) rs += fabs(A[i * 9 + j]);
            if (rs > nrm) nrm = rs;
        }
        int s = 0;
        while (nrm > 0.5 && s < 60) { nrm *= 0.5; s++; }
        ssc = s;
    }
    __syncthreads();
    const int s = ssc;
    if (t < 81) {
        A[t] = ldexp(A[t], -s);
        M[t] = ((t % 10 == 0) ? 1.0 : 0.0) + A[t];
        P[t] = A[t];
    }
    __syncthreads();
    for (int it = 2; it <= 22; it++) {
        if (t < 81) {
            int i = t / 9, j = t % 9;
            double acc = 0.0;
            #pragma unroll
            for (int kk = 0; kk < 9; kk++) acc += P[i * 9 + kk] * A[kk * 9 + j];
            Pn[t] = acc / (double)it;
        }
        __syncthreads();
        if (t < 81) { P[t] = Pn[t]; M[t] += P[t]; }
        __syncthreads();
    }
    for (int qq = 0; qq < s; qq++) {
        if (t < 81) {
            int i = t / 9, j = t % 9;
            double acc = 0.0;
            #pragma unroll
            for (int kk = 0; kk < 9; kk++) acc += M[i * 9 + kk] * M[kk * 9 + j];
            Pn[t] = acc;
        }
        __syncthreads();
        if (t < 81) M[t] = Pn[t];
        __syncthreads();
    }
    if (t < 8) {
        double coord = M[t * 9 + 8];
        g_cf[b][t] = (float)(coord * (double)g_vnorm[b] * (double)g_inv[t][b]);
    }
}

// ---------------- final combine (float4, fp32 Q; per-batch) ----------------
__global__ void __launch_bounds__(256) k_combine(const float* __restrict__ v,
                                                 float* __restrict__ out, int b) {
    size_t idx = (size_t)b * PER_B + ((size_t)blockIdx.x * 256 + threadIdx.x) * 4;
    float cf[8];
    #pragma unroll
    for (int j = 0; j < 8; j++) cf[j] = g_cf[b][j];
    float4 x = make_float4(0.f, 0.f, 0.f, 0.f);
    #pragma unroll
    for (int j = 0; j < 8; j++) {
        const float* qs = (j == 0) ? v : g_Q[j - 1];
        float4 q = *(const float4*)(qs + idx);
        x.x += cf[j] * q.x; x.y += cf[j] * q.y;
        x.z += cf[j] * q.z; x.w += cf[j] * q.w;
    }
    *(float4*)(out + idx) = x;
}

// dummy join kernel (makes the final join visible to the captured graph cheaply)
__global__ void k_nop() {}

// ---------------- driver: 8 streams x 1 batch, fork/join via events ----------------
extern "C" void kernel_launch(void* const* d_in, const int* in_sizes, int n_in,
                              void* d_out, int out_size) {
    const float* s0 = (const float*)d_in[0];
    const float* v  = (const float*)d_in[1];
    const float* Wm = (const float*)d_in[2];
    float* out = (float*)d_out;

    const int GEMM_SMEM = 2 * STG_SZ;   // 67584
    cudaFuncSetAttribute(k_gemm_fused, cudaFuncAttributeMaxDynamicSharedMemorySize, GEMM_SMEM);

    dim3 gP(HW / 32);                // per-batch: 128 p-tiles
    dim3 gGemm(HW / 128, 2);         // per-batch: 32 p-tiles x 2 m-tiles
    dim3 gComb(PER_B / 1024);        // per-batch combine

    k_splitW<<<Cc * Cc / 256, 256>>>(Wm);
    cudaEventRecord(g_si.root, 0);

    for (int s = 0; s < 8; s++) {
        cudaStream_t st = g_si.st[s];
        const int b = s;
        cudaStreamWaitEvent(st, g_si.root, 0);
        k_repl0<<<gP, 256, 0, st>>>(s0, v, b);
        for (int k = 0; k < 8; k++) {
            k_gemm_fused<<<gGemm, 256, GEMM_SMEM, st>>>(v, k, (k < 7) ? 1 : 0, b);
            if (k < 7) k_upd_repl<<<gP, 256, 0, st>>>(s0, v, k, b);
        }
        k_expm<<<1, 128, 0, st>>>(b);
        k_combine<<<gComb, 256, 0, st>>>(v, out, b);
        cudaEventRecord(g_si.join[s], st);
    }

    for (int s = 0; s < 8; s++) cudaStreamWaitEvent(0, g_si.join[s], 0);
    k_nop<<<1, 32>>>();
}

// round 14
// speedup vs baseline: 1.3403x; 1.0386x over previous
#include <cuda_runtime.h>
#include <cuda_bf16.h>
#include <math.h>
#include <stdint.h>

#define Bb    8
#define Cc    256
#define HW    4096
#define PER_B (Cc * HW)          // 2^20
#define EPSF  1e-12f

// ---------------- device scratch ----------------
__device__ float g_Q[7][Bb * PER_B];   // unnormalized Krylov vectors fp32, slots 1..7 (slot 0 = input v)
__device__ __nv_bfloat16 g_Qbf[8][Bb * PER_B]; // bf16 mirror of Qu_j (slot 0 = bf16(v)) for dots
__device__ float g_w[Bb * PER_B];      // GEMM output (scaled by inv_k)
__device__ __nv_bfloat16 g_Rhi[Bb * PER_B];  // replicator out, layout [b][c][p] (p contiguous), hi
__device__ __nv_bfloat16 g_Rlo[Bb * PER_B];  // lo residual
__device__ __nv_bfloat16 g_Whi[Cc * Cc];
__device__ __nv_bfloat16 g_Wlo[Cc * Cc];
__device__ float g_dpart[8][Bb][64];   // raw dot partials [j][b][mt*32+pblock]
__device__ float g_npart[Bb][128];     // norm partials
__device__ float g_H[Bb][8][8];
__device__ float g_inv[8][Bb];
__device__ float g_vnorm[Bb];
__device__ float g_cf[Bb][8];

// ---------------- stream/event infra (created once at load; no device memory) ----------------
namespace {
struct StreamInit {
    cudaStream_t st[8];
    cudaEvent_t  root;
    cudaEvent_t  join[8];
    cudaEvent_t  stg[4];
    StreamInit() {
        for (int i = 0; i < 8; i++) cudaStreamCreateWithFlags(&st[i], cudaStreamNonBlocking);
        cudaEventCreateWithFlags(&root, cudaEventDisableTiming);
        for (int i = 0; i < 8; i++) cudaEventCreateWithFlags(&join[i], cudaEventDisableTiming);
        for (int i = 0; i < 4; i++) cudaEventCreateWithFlags(&stg[i], cudaEventDisableTiming);
    }
};
StreamInit g_si;
}

// ---------------- PTX helpers ----------------
static __device__ __forceinline__ uint32_t smem_u32(const void* p) {
    uint32_t a;
    asm("{ .reg .u64 t; cvta.to.shared.u64 t, %1; cvt.u32.u64 %0, t; }" : "=r"(a) : "l"(p));
    return a;
}
#define CP16(dst, src) \
    asm volatile("cp.async.cg.shared.global [%0], [%1], 16;" :: "r"(dst), "l"(src))
#define CP_COMMIT() asm volatile("cp.async.commit_group;" ::: "memory")
#define CP_WAIT0()  asm volatile("cp.async.wait_group 0;" ::: "memory")
#define LDSM4(r0, r1, r2, r3, addr) \
    asm volatile("ldmatrix.sync.aligned.m8n8.x4.shared.b16 {%0,%1,%2,%3}, [%4];" \
        : "=r"(r0), "=r"(r1), "=r"(r2), "=r"(r3) : "r"(addr))
#define LDSM4T(r0, r1, r2, r3, addr) \
    asm volatile("ldmatrix.sync.aligned.m8n8.x4.trans.shared.b16 {%0,%1,%2,%3}, [%4];" \
        : "=r"(r0), "=r"(r1), "=r"(r2), "=r"(r3) : "r"(addr))

static __device__ __forceinline__ void mma_bf16(float* c, const uint32_t* a, const uint32_t* b) {
    asm volatile("mma.sync.aligned.m16n8k16.row.col.f32.bf16.bf16.f32 "
        "{%0,%1,%2,%3}, {%4,%5,%6,%7}, {%8,%9}, {%0,%1,%2,%3};"
        : "+f"(c[0]), "+f"(c[1]), "+f"(c[2]), "+f"(c[3])
        : "r"(a[0]), "r"(a[1]), "r"(a[2]), "r"(a[3]), "r"(b[0]), "r"(b[1]));
}

static __device__ __forceinline__ float warpReduce(float v) {
    #pragma unroll
    for (int off = 16; off > 0; off >>= 1) v += __shfl_xor_sync(0xFFFFFFFFu, v, off);
    return v;
}

static __device__ __forceinline__ uint32_t pack_hi(float a, float b) {
    __nv_bfloat16 ha = __float2bfloat16(a), hb = __float2bfloat16(b);
    return (uint32_t)__bfloat16_as_ushort(ha) | ((uint32_t)__bfloat16_as_ushort(hb) << 16);
}
static __device__ __forceinline__ uint32_t pack_lo(float a, float b) {
    __nv_bfloat16 ha = __float2bfloat16(a), hb = __float2bfloat16(b);
    float la = a - __bfloat162float(ha), lb = b - __bfloat162float(hb);
    __nv_bfloat16 pa = __float2bfloat16(la), pb = __float2bfloat16(lb);
    return (uint32_t)__bfloat16_as_ushort(pa) | ((uint32_t)__bfloat16_as_ushort(pb) << 16);
}

// ---------------- W split to bf16 hi/lo ----------------
__global__ void __launch_bounds__(256) k_splitW(const float* __restrict__ Wm) {
    int i = blockIdx.x * 256 + threadIdx.x;
    float x = Wm[i];
    __nv_bfloat16 h = __float2bfloat16(x);
    g_Whi[i] = h;
    g_Wlo[i] = __float2bfloat16(x - __bfloat162float(h));
}

// ---------------- step-0 replicator: R(v) + Qbf0 + ||v||^2 partials (32p x 256c, 256 thr) ----------------
__global__ void __launch_bounds__(256, 2) k_repl0(const float* __restrict__ s0,
                                                  const float* __restrict__ v, int b) {
    const int t = threadIdx.x, lane = t & 31, wid = t >> 5;
    const int pq = t & 7;           // p-quad (8 quads = 32 p)
    const int cg = t >> 3;          // 0..31 c-groups
    const int p0 = blockIdx.x * 32;
    const size_t base = (size_t)b * PER_B + p0 + pq * 4;

    __shared__ float4 Sred[32][8];
    __shared__ float4 Ssm[8];
    __shared__ float  nsh[8];

    float4 xv[8];
    float4 Sacc = make_float4(0.f, 0.f, 0.f, 0.f);
    float nacc = 0.f;
    #pragma unroll
    for (int i = 0; i < 8; i++) {
        size_t off = base + (size_t)(cg + 32 * i) * HW;
        float4 x4 = *(const float4*)(v + off);
        float4 s4 = *(const float4*)(s0 + off);
        xv[i] = x4;
        Sacc.x += s4.x * x4.x; Sacc.y += s4.y * x4.y;
        Sacc.z += s4.z * x4.z; Sacc.w += s4.w * x4.w;
        nacc += x4.x * x4.x + x4.y * x4.y + x4.z * x4.z + x4.w * x4.w;
    }
    Sred[cg][pq] = Sacc;
    nacc = warpReduce(nacc);
    if (lane == 0) nsh[wid] = nacc;
    __syncthreads();
    if (t < 8) {
        float4 s = make_float4(0.f, 0.f, 0.f, 0.f);
        #pragma unroll
        for (int g2 = 0; g2 < 32; g2++) {
            float4 a = Sred[g2][t];
            s.x += a.x; s.y += a.y; s.z += a.z; s.w += a.w;
        }
        Ssm[t] = s;
    }
    if (t == 8) {
        float s = 0.f;
        #pragma unroll
        for (int w2 = 0; w2 < 8; w2++) s += nsh[w2];
        g_npart[b][blockIdx.x] = s;
    }
    __syncthreads();
    float4 S4 = Ssm[pq];
    #pragma unroll
    for (int i = 0; i < 8; i++) {
        size_t off = base + (size_t)(cg + 32 * i) * HW;
        float4 s4 = *(const float4*)(s0 + off);          // L2-hot
        float rx = s4.x * (xv[i].x - S4.x), ry = s4.y * (xv[i].y - S4.y);
        float rz = s4.z * (xv[i].z - S4.z), rw = s4.w * (xv[i].w - S4.w);
        *(uint2*)(g_Rhi + off)    = make_uint2(pack_hi(rx, ry), pack_hi(rz, rw));
        *(uint2*)(g_Rlo + off)    = make_uint2(pack_lo(rx, ry), pack_lo(rz, rw));
        *(uint2*)(g_Qbf[0] + off) = make_uint2(pack_hi(xv[i].x, xv[i].y), pack_hi(xv[i].z, xv[i].w));
    }
}

// ---------------- fused update + replicator + dots_fin + norm (k = 0..6) ----------------
__global__ void __launch_bounds__(256, 2) k_upd_repl(const float* __restrict__ s0,
                                                     const float* __restrict__ v, int k, int b) {
    const int t = threadIdx.x, lane = t & 31, wid = t >> 5;
    const int pq = t & 7;
    const int cg = t >> 3;
    const int p0 = blockIdx.x * 32;
    const size_t base = (size_t)b * PER_B + p0 + pq * 4;

    __shared__ float  hc[8];
    __shared__ float4 Sred[32][8];
    __shared__ float4 Ssm[8];
    __shared__ float  nsh[8];

    // inline dots finalize: warp j (j<=k<=6, 8 warps) reduces 64 partials -> hcoef
    if (wid <= k) {
        float dv = g_dpart[wid][b][lane] + g_dpart[wid][b][lane + 32];
        dv = warpReduce(dv);
        if (lane == 0) {
            float invj = g_inv[wid][b];
            float h = dv * invj;
            hc[wid] = h * invj;
            if (blockIdx.x == 0) g_H[b][wid][k] = h;
        }
    }
    __syncthreads();

    float4 xv[8];
    #pragma unroll
    for (int i = 0; i < 8; i++) {
        size_t off = base + (size_t)(cg + 32 * i) * HW;
        xv[i] = *(const float4*)(g_w + off);
    }
    for (int j = 0; j <= k; j++) {
        const float* __restrict__ Qj = (j == 0) ? v : g_Q[j - 1];
        float cf = hc[j];
        #pragma unroll
        for (int i = 0; i < 8; i++) {
            size_t off = base + (size_t)(cg + 32 * i) * HW;
            float4 q = *(const float4*)(Qj + off);
            xv[i].x -= cf * q.x; xv[i].y -= cf * q.y;
            xv[i].z -= cf * q.z; xv[i].w -= cf * q.w;
        }
    }

    float* __restrict__ qn = g_Q[k];
    __nv_bfloat16* __restrict__ qb = g_Qbf[k + 1];
    float4 Sacc = make_float4(0.f, 0.f, 0.f, 0.f);
    float nacc = 0.f;
    #pragma unroll
    for (int i = 0; i < 8; i++) {
        size_t off = base + (size_t)(cg + 32 * i) * HW;
        *(float4*)(qn + off) = xv[i];
        *(uint2*)(qb + off)  = make_uint2(pack_hi(xv[i].x, xv[i].y), pack_hi(xv[i].z, xv[i].w));
        float4 s4 = *(const float4*)(s0 + off);
        Sacc.x += s4.x * xv[i].x; Sacc.y += s4.y * xv[i].y;
        Sacc.z += s4.z * xv[i].z; Sacc.w += s4.w * xv[i].w;
        nacc += xv[i].x * xv[i].x + xv[i].y * xv[i].y
              + xv[i].z * xv[i].z + xv[i].w * xv[i].w;
    }
    Sred[cg][pq] = Sacc;
    nacc = warpReduce(nacc);
    if (lane == 0) nsh[wid] = nacc;
    __syncthreads();
    if (t < 8) {
        float4 s = make_float4(0.f, 0.f, 0.f, 0.f);
        #pragma unroll
        for (int g2 = 0; g2 < 32; g2++) {
            float4 a = Sred[g2][t];
            s.x += a.x; s.y += a.y; s.z += a.z; s.w += a.w;
        }
        Ssm[t] = s;
    }
    if (t == 8) {
        float s = 0.f;
        #pragma unroll
        for (int w2 = 0; w2 < 8; w2++) s += nsh[w2];
        g_npart[b][blockIdx.x] = s;
    }
    __syncthreads();
    float4 S4 = Ssm[pq];
    #pragma unroll
    for (int i = 0; i < 8; i++) {
        size_t off = base + (size_t)(cg + 32 * i) * HW;
        float4 s4 = *(const float4*)(s0 + off);          // L2-hot re-read
        float rx = s4.x * (xv[i].x - S4.x), ry = s4.y * (xv[i].y - S4.y);
        float rz = s4.z * (xv[i].z - S4.z), rw = s4.w * (xv[i].w - S4.w);
        *(uint2*)(g_Rhi + off) = make_uint2(pack_hi(rx, ry), pack_hi(rz, rw));
        *(uint2*)(g_Rlo + off) = make_uint2(pack_lo(rx, ry), pack_lo(rz, rw));
    }
}

// ---------------- fused GEMM + dots (2-stage pipeline, bf16 dot reads, inline norm finalize) ----------------
static __device__ __forceinline__ void cp_tileA(uint32_t dstbase, const __nv_bfloat16* src,
                                                int kc, int tid) {
    #pragma unroll
    for (int i = 0; i < 2; i++) {
        int x   = tid + (i << 8);     // 0..511 16B chunks
        int row = x >> 2;             // 0..127
        int cb  = (x & 3) << 4;       // 0,16,32,48
        const char* gp = (const char*)(src + (size_t)row * 256 + kc) + cb;
        uint32_t dp = dstbase + (uint32_t)(row * 64 + (cb ^ (((row >> 1) & 3) << 4)));
        CP16(dp, gp);
    }
}
static __device__ __forceinline__ void cp_tileB(uint32_t dstbase, const __nv_bfloat16* srcb,
                                                int kc, int tid) {
    #pragma unroll
    for (int i = 0; i < 2; i++) {
        int x   = tid + (i << 8);     // 0..511
        int row = x >> 4;             // 0..31 (c within chunk)
        int cb  = (x & 15) << 4;      // byte col 0..240
        const char* gp = (const char*)(srcb + (size_t)(kc + row) * HW) + cb;
        CP16(dstbase + (uint32_t)(row * 272 + cb), gp);
    }
}

#define STG_SZ 33792   // per-stage: AH 8192 + AL 8192 + BH 8704 + BL 8704

__global__ void __launch_bounds__(256, 2) k_gemm_fused(const float* __restrict__ v,
                                                       int kstep, int write_w, int b, int full3) {
    extern __shared__ __align__(128) char smem[];
    const int tid  = threadIdx.x;
    const int wid  = tid >> 5;
    const int lane = tid & 31;
    const int g    = lane >> 2;
    const int q    = lane & 3;
    const int l8   = lane & 7;
    const int g8   = lane >> 3;
    const int wm   = wid >> 2;       // 0..1
    const int wn   = wid & 3;        // 0..3
    const int p0   = blockIdx.x * 128;
    const int mt   = blockIdx.y;

    uint32_t sb = smem_u32(smem);

    const __nv_bfloat16* Whi = g_Whi + (size_t)mt * 128 * 256;
    const __nv_bfloat16* Wlo = g_Wlo + (size_t)mt * 128 * 256;
    const __nv_bfloat16* RhiB = g_Rhi + (size_t)b * PER_B + p0;
    const __nv_bfloat16* RloB = g_Rlo + (size_t)b * PER_B + p0;
    const size_t qtile = (size_t)b * PER_B + (size_t)(mt * 128) * HW + p0;

    // prologue: chunk 0 into stage 0
    cp_tileA(sb,         Whi,  0, tid);
    cp_tileB(sb + 16384, RhiB, 0, tid);
    if (full3) {
        cp_tileA(sb + 8192,  Wlo,  0, tid);
        cp_tileB(sb + 25088, RloB, 0, tid);
    }
    CP_COMMIT();

    // inline norm finalize -> inv_k (overlaps chunk-0 load); 128 partials
    __shared__ float invsh;
    __shared__ float rsh[4];
    if (tid < 128) {
        float val = warpReduce(g_npart[b][tid]);
        if (lane == 0) rsh[wid] = val;
    }
    __syncthreads();
    if (tid == 0) {
        float hn = sqrtf(rsh[0] + rsh[1] + rsh[2] + rsh[3]);
        float iv = (kstep == 0) ? (1.f / hn) : (1.f / (hn + EPSF));
        invsh = iv;
        if (blockIdx.x == 0 && blockIdx.y == 0) {
            g_inv[kstep][b] = iv;
            if (kstep == 0) g_vnorm[b] = hn;
            else            g_H[b][kstep][kstep - 1] = hn;
        }
    }

    float acc[4][4][4];
    #pragma unroll
    for (int i = 0; i < 4; i++)
        #pragma unroll
        for (int j = 0; j < 4; j++)
            #pragma unroll
            for (int e = 0; e < 4; e++) acc[i][j][e] = 0.f;

    const uint32_t aR0 = (uint32_t)(wm * 64 + (g8 & 1) * 8 + l8);
    const uint32_t aK  = (uint32_t)(g8 >> 1) << 4;
    const uint32_t bRow = (uint32_t)(((lane >> 3) & 1) * 8 + l8);
    const uint32_t bCol = (uint32_t)(wn * 64) + ((uint32_t)(lane >> 4)) * 16;

    #pragma unroll
    for (int ci = 0; ci < 8; ci++) {
        CP_WAIT0();
        __syncthreads();
        if (ci < 7) {
            uint32_t st = sb + (uint32_t)(((ci + 1) & 1) * STG_SZ);
            int kc = (ci + 1) * 32;
            cp_tileA(st,         Whi,  kc, tid);
            cp_tileB(st + 16384, RhiB, kc, tid);
            if (full3) {
                cp_tileA(st + 8192,  Wlo,  kc, tid);
                cp_tileB(st + 25088, RloB, kc, tid);
            }
            CP_COMMIT();
        }
        const uint32_t ST = sb + (uint32_t)((ci & 1) * STG_SZ);
        const uint32_t AHs = ST, ALs = ST + 8192, BHs = ST + 16384, BLs = ST + 25088;

        #pragma unroll
        for (int kf = 0; kf < 2; kf++) {
            const uint32_t cbA = (uint32_t)(kf * 32) + aK;
            uint32_t ah[4][4], al[4][4], bh[4][2], bl[4][2];
            #pragma unroll
            for (int mf = 0; mf < 4; mf++) {
                uint32_t r  = aR0 + (uint32_t)(mf * 16);
                uint32_t ao = r * 64 + (cbA ^ (((r >> 1) & 3) << 4));
                LDSM4(ah[mf][0], ah[mf][1], ah[mf][2], ah[mf][3], AHs + ao);
            }
            #pragma unroll
            for (int j2 = 0; j2 < 2; j2++) {
                uint32_t bo = (uint32_t)(kf * 16 + bRow) * 272 + bCol + (uint32_t)(j2 * 32);
                LDSM4T(bh[2*j2][0], bh[2*j2][1], bh[2*j2+1][0], bh[2*j2+1][1], BHs + bo);
            }
            #pragma unroll
            for (int mf = 0; mf < 4; mf++)
                #pragma unroll
                for (int nf = 0; nf < 4; nf++)
                    mma_bf16(acc[mf][nf], ah[mf], bh[nf]);   // Whi*Rhi
            if (full3) {
                #pragma unroll
                for (int mf = 0; mf < 4; mf++) {
                    uint32_t r  = aR0 + (uint32_t)(mf * 16);
                    uint32_t ao = r * 64 + (cbA ^ (((r >> 1) & 3) << 4));
                    LDSM4(al[mf][0], al[mf][1], al[mf][2], al[mf][3], ALs + ao);
                }
                #pragma unroll
                for (int j2 = 0; j2 < 2; j2++) {
                    uint32_t bo = (uint32_t)(kf * 16 + bRow) * 272 + bCol + (uint32_t)(j2 * 32);
                    LDSM4T(bl[2*j2][0], bl[2*j2][1], bl[2*j2+1][0], bl[2*j2+1][1], BLs + bo);
                }
                #pragma unroll
                for (int mf = 0; mf < 4; mf++)
                    #pragma unroll
                    for (int nf = 0; nf < 4; nf++) {
                        mma_bf16(acc[mf][nf], al[mf], bh[nf]);   // Wlo*Rhi
                        mma_bf16(acc[mf][nf], ah[mf], bl[nf]);   // Whi*Rlo
                    }
            }
        }
    }

    // scale by inv_k (deferred normalization of q_k)
    const float inv = invsh;
    #pragma unroll
    for (int mf = 0; mf < 4; mf++)
        #pragma unroll
        for (int nf = 0; nf < 4; nf++)
            #pragma unroll
            for (int e = 0; e < 4; e++) acc[mf][nf][e] *= inv;

    if (write_w) {
        float* dst = g_w + qtile;
        #pragma unroll
        for (int mf = 0; mf < 4; mf++) {
            int m = wm * 64 + mf * 16 + g;
            #pragma unroll
            for (int nf = 0; nf < 4; nf++) {
                int pp = wn * 32 + nf * 8 + q * 2;
                *(float2*)(dst + (size_t)m * HW + pp)       = make_float2(acc[mf][nf][0], acc[mf][nf][1]);
                *(float2*)(dst + (size_t)(m + 8) * HW + pp) = make_float2(acc[mf][nf][2], acc[mf][nf][3]);
            }
        }
    }

    // fused dots vs bf16 Q mirror: raw partial <Qbf_j, w> over this CTA's 128x128 tile
    __shared__ float dsh[8][8];
    for (int j = 0; j <= kstep; j++) {
        const __nv_bfloat16* Qb = g_Qbf[j] + qtile;
        float d = 0.f;
        #pragma unroll
        for (int mf = 0; mf < 4; mf++) {
            int m = wm * 64 + mf * 16 + g;
            #pragma unroll
            for (int nf = 0; nf < 4; nf++) {
                int pp = wn * 32 + nf * 8 + q * 2;
                float2 a0 = __bfloat1622float2(*(const __nv_bfloat162*)(Qb + (size_t)m * HW + pp));
                float2 a1 = __bfloat1622float2(*(const __nv_bfloat162*)(Qb + (size_t)(m + 8) * HW + pp));
                d += acc[mf][nf][0] * a0.x + acc[mf][nf][1] * a0.y
                   + acc[mf][nf][2] * a1.x + acc[mf][nf][3] * a1.y;
            }
        }
        d = warpReduce(d);
        if (lane == 0) dsh[j][wid] = d;
    }
    __syncthreads();
    if (tid < 64) {
        int j = tid >> 3, w8 = tid & 7;
        float val = (j <= kstep) ? dsh[j][w8] : 0.f;
        #pragma unroll
        for (int off = 4; off > 0; off >>= 1) val += __shfl_xor_sync(0xFFFFFFFFu, val, off);
        if (w8 == 0 && j <= kstep) g_dpart[j][b][mt * 32 + blockIdx.x] = val;
    }
}

// ---------------- expm of 9x9 (scaling-squaring + Taylor, fp64) + H col 7 finalize ----------------
__global__ void k_expm(int b) {
    const int t = threadIdx.x;
    __shared__ double A[81], M[81], P[81], Pn[81];
    __shared__ float Hc7[8];
    __shared__ int ssc;

    if (t < 8) {
        float dv = 0.f;
        for (int i2 = 0; i2 < 64; i2++) dv += g_dpart[t][b][i2];
        Hc7[t] = dv * g_inv[t][b];
    }
    __syncthreads();

    if (t < 81) {
        int i = t / 9, j = t % 9;
        double e = 0.0;
        if (i < 8 && j < 8) e = (j == 7) ? (double)Hc7[i] : (double)g_H[b][i][j];
        if (i == 0 && j == 8) e = 1.0;
        A[t] = e;
    }
    __syncthreads();
    if (t == 0) {
        double nrm = 0.0;
        for (int i = 0; i < 9; i++) {
            double rs = 0.0;
            for (int j = 0; j < 9; j++) rs += fabs(A[i * 9 + j]);
            if (rs > nrm) nrm = rs;
        }
        int s = 0;
        while (nrm > 0.5 && s < 60) { nrm *= 0.5; s++; }
        ssc = s;
    }
    __syncthreads();
    const int s = ssc;
    if (t < 81) {
        A[t] = ldexp(A[t], -s);
        M[t] = ((t % 10 == 0) ? 1.0 : 0.0) + A[t];
        P[t] = A[t];
    }
    __syncthreads();
    for (int it = 2; it <= 22; it++) {
        if (t < 81) {
            int i = t / 9, j = t % 9;
            double acc = 0.0;
            #pragma unroll
            for (int kk = 0; kk < 9; kk++) acc += P[i * 9 + kk] * A[kk * 9 + j];
            Pn[t] = acc / (double)it;
        }
        __syncthreads();
        if (t < 81) { P[t] = Pn[t]; M[t] += P[t]; }
        __syncthreads();
    }
    for (int qq = 0; qq < s; qq++) {
        if (t < 81) {
            int i = t / 9, j = t % 9;
            double acc = 0.0;
            #pragma unroll
            for (int kk = 0; kk < 9; kk++) acc += M[i * 9 + kk] * M[kk * 9 + j];
            Pn[t] = acc;
        }
        __syncthreads();
        if (t < 81) M[t] = Pn[t];
        __syncthreads();
    }
    if (t < 8) {
        double coord = M[t * 9 + 8];
        g_cf[b][t] = (float)(coord * (double)g_vnorm[b] * (double)g_inv[t][b]);
    }
}

// ---------------- final combine (float4, fp32 Q; per-batch) ----------------
__global__ void __launch_bounds__(256) k_combine(const float* __restrict__ v,
                                                 float* __restrict__ out, int b) {
    size_t idx = (size_t)b * PER_B + ((size_t)blockIdx.x * 256 + threadIdx.x) * 4;
    float cf[8];
    #pragma unroll
    for (int j = 0; j < 8; j++) cf[j] = g_cf[b][j];
    float4 x = make_float4(0.f, 0.f, 0.f, 0.f);
    #pragma unroll
    for (int j = 0; j < 8; j++) {
        const float* qs = (j == 0) ? v : g_Q[j - 1];
        float4 q = *(const float4*)(qs + idx);
        x.x += cf[j] * q.x; x.y += cf[j] * q.y;
        x.z += cf[j] * q.z; x.w += cf[j] * q.w;
    }
    *(float4*)(out + idx) = x;
}

// dummy join kernel (makes the final join visible to the captured graph cheaply)
__global__ void k_nop() {}

// ---------------- driver: 8 streams x 1 batch, phase-staggered, fork/join via events ----------------
extern "C" void kernel_launch(void* const* d_in, const int* in_sizes, int n_in,
                              void* d_out, int out_size) {
    const float* s0 = (const float*)d_in[0];
    const float* v  = (const float*)d_in[1];
    const float* Wm = (const float*)d_in[2];
    float* out = (float*)d_out;

    const int GEMM_SMEM = 2 * STG_SZ;   // 67584
    cudaFuncSetAttribute(k_gemm_fused, cudaFuncAttributeMaxDynamicSharedMemorySize, GEMM_SMEM);

    dim3 gP(HW / 32);                // per-batch: 128 p-tiles
    dim3 gGemm(HW / 128, 2);         // per-batch: 32 p-tiles x 2 m-tiles
    dim3 gComb(PER_B / 1024);        // per-batch combine

    k_splitW<<<Cc * Cc / 256, 256>>>(Wm);
    cudaEventRecord(g_si.root, 0);

    for (int s = 0; s < 8; s++) {
        cudaStream_t st = g_si.st[s];
        const int b = s;
        cudaStreamWaitEvent(st, g_si.root, 0);
        k_repl0<<<gP, 256, 0, st>>>(s0, v, b);
        // phase stagger: streams 4..7 start their GEMM chain one gemm-phase later
        if (s >= 4) cudaStreamWaitEvent(st, g_si.stg[s - 4], 0);
        for (int k = 0; k < 8; k++) {
            int full3 = (k < 7) ? 1 : 0;
            k_gemm_fused<<<gGemm, 256, GEMM_SMEM, st>>>(v, k, (k < 7) ? 1 : 0, b, full3);
            if (s < 4 && k == 0) cudaEventRecord(g_si.stg[s], st);
            if (k < 7) k_upd_repl<<<gP, 256, 0, st>>>(s0, v, k, b);
        }
        k_expm<<<1, 128, 0, st>>>(b);
        k_combine<<<gComb, 256, 0, st>>>(v, out, b);
        cudaEventRecord(g_si.join[s], st);
    }

    for (int s = 0; s < 8; s++) cudaStreamWaitEvent(0, g_si.join[s], 0);
    k_nop<<<1, 32>>>();
}

// round 15
// speedup vs baseline: 1.3450x; 1.0035x over previous
#include <cuda_runtime.h>
#include <cuda_bf16.h>
#include <math.h>
#include <stdint.h>

#define Bb    8
#define Cc    256
#define HW    4096
#define PER_B (Cc * HW)          // 2^20
#define EPSF  1e-12f

// ---------------- device scratch ----------------
__device__ float g_Q[7][Bb * PER_B];   // unnormalized Krylov vectors fp32, slots 1..6 used (slot 0 = input v; Q7 bf16-only)
__device__ __nv_bfloat16 g_Qbf[8][Bb * PER_B]; // bf16 mirror of Qu_j (slot 0 = bf16(v)) for dots / Q7 combine
__device__ float g_w[Bb * PER_B];      // GEMM output (scaled by inv_k)
__device__ __nv_bfloat16 g_Rhi[Bb * PER_B];  // replicator out, layout [b][c][p] (p contiguous), hi
__device__ __nv_bfloat16 g_Rlo[Bb * PER_B];  // lo residual
__device__ __nv_bfloat16 g_Whi[Cc * Cc];
__device__ __nv_bfloat16 g_Wlo[Cc * Cc];
__device__ float g_dpart[8][Bb][64];   // raw dot partials [j][b][mt*32+pblock]
__device__ float g_npart[Bb][128];     // norm partials
__device__ float g_H[Bb][8][8];
__device__ float g_inv[8][Bb];
__device__ float g_vnorm[Bb];
__device__ float g_cf[Bb][8];

// ---------------- stream/event infra (created once at load; no device memory) ----------------
namespace {
struct StreamInit {
    cudaStream_t st[8];
    cudaEvent_t  root;
    cudaEvent_t  join[8];
    cudaEvent_t  stg[4];
    StreamInit() {
        for (int i = 0; i < 8; i++) cudaStreamCreateWithFlags(&st[i], cudaStreamNonBlocking);
        cudaEventCreateWithFlags(&root, cudaEventDisableTiming);
        for (int i = 0; i < 8; i++) cudaEventCreateWithFlags(&join[i], cudaEventDisableTiming);
        for (int i = 0; i < 4; i++) cudaEventCreateWithFlags(&stg[i], cudaEventDisableTiming);
    }
};
StreamInit g_si;
}

// ---------------- PTX helpers ----------------
static __device__ __forceinline__ uint32_t smem_u32(const void* p) {
    uint32_t a;
    asm("{ .reg .u64 t; cvta.to.shared.u64 t, %1; cvt.u32.u64 %0, t; }" : "=r"(a) : "l"(p));
    return a;
}
#define CP16(dst, src) \
    asm volatile("cp.async.cg.shared.global [%0], [%1], 16;" :: "r"(dst), "l"(src))
#define CP_COMMIT() asm volatile("cp.async.commit_group;" ::: "memory")
#define CP_WAIT0()  asm volatile("cp.async.wait_group 0;" ::: "memory")
#define LDSM4(r0, r1, r2, r3, addr) \
    asm volatile("ldmatrix.sync.aligned.m8n8.x4.shared.b16 {%0,%1,%2,%3}, [%4];" \
        : "=r"(r0), "=r"(r1), "=r"(r2), "=r"(r3) : "r"(addr))
#define LDSM4T(r0, r1, r2, r3, addr) \
    asm volatile("ldmatrix.sync.aligned.m8n8.x4.trans.shared.b16 {%0,%1,%2,%3}, [%4];" \
        : "=r"(r0), "=r"(r1), "=r"(r2), "=r"(r3) : "r"(addr))

static __device__ __forceinline__ void mma_bf16(float* c, const uint32_t* a, const uint32_t* b) {
    asm volatile("mma.sync.aligned.m16n8k16.row.col.f32.bf16.bf16.f32 "
        "{%0,%1,%2,%3}, {%4,%5,%6,%7}, {%8,%9}, {%0,%1,%2,%3};"
        : "+f"(c[0]), "+f"(c[1]), "+f"(c[2]), "+f"(c[3])
        : "r"(a[0]), "r"(a[1]), "r"(a[2]), "r"(a[3]), "r"(b[0]), "r"(b[1]));
}

static __device__ __forceinline__ float warpReduce(float v) {
    #pragma unroll
    for (int off = 16; off > 0; off >>= 1) v += __shfl_xor_sync(0xFFFFFFFFu, v, off);
    return v;
}

static __device__ __forceinline__ uint32_t pack_hi(float a, float b) {
    __nv_bfloat16 ha = __float2bfloat16(a), hb = __float2bfloat16(b);
    return (uint32_t)__bfloat16_as_ushort(ha) | ((uint32_t)__bfloat16_as_ushort(hb) << 16);
}
static __device__ __forceinline__ uint32_t pack_lo(float a, float b) {
    __nv_bfloat16 ha = __float2bfloat16(a), hb = __float2bfloat16(b);
    float la = a - __bfloat162float(ha), lb = b - __bfloat162float(hb);
    __nv_bfloat16 pa = __float2bfloat16(la), pb = __float2bfloat16(lb);
    return (uint32_t)__bfloat16_as_ushort(pa) | ((uint32_t)__bfloat16_as_ushort(pb) << 16);
}

// ---------------- W split to bf16 hi/lo ----------------
__global__ void __launch_bounds__(256) k_splitW(const float* __restrict__ Wm) {
    int i = blockIdx.x * 256 + threadIdx.x;
    float x = Wm[i];
    __nv_bfloat16 h = __float2bfloat16(x);
    g_Whi[i] = h;
    g_Wlo[i] = __float2bfloat16(x - __bfloat162float(h));
}

// ---------------- step-0 replicator: R(v) + Qbf0 + ||v||^2 partials (32p x 256c, 256 thr) ----------------
__global__ void __launch_bounds__(256, 2) k_repl0(const float* __restrict__ s0,
                                                  const float* __restrict__ v, int b) {
    const int t = threadIdx.x, lane = t & 31, wid = t >> 5;
    const int pq = t & 7;           // p-quad (8 quads = 32 p)
    const int cg = t >> 3;          // 0..31 c-groups
    const int p0 = blockIdx.x * 32;
    const size_t base = (size_t)b * PER_B + p0 + pq * 4;

    __shared__ float4 Sred[32][8];
    __shared__ float4 Ssm[8];
    __shared__ float  nsh[8];

    float4 xv[8];
    float4 Sacc = make_float4(0.f, 0.f, 0.f, 0.f);
    float nacc = 0.f;
    #pragma unroll
    for (int i = 0; i < 8; i++) {
        size_t off = base + (size_t)(cg + 32 * i) * HW;
        float4 x4 = *(const float4*)(v + off);
        float4 s4 = *(const float4*)(s0 + off);
        xv[i] = x4;
        Sacc.x += s4.x * x4.x; Sacc.y += s4.y * x4.y;
        Sacc.z += s4.z * x4.z; Sacc.w += s4.w * x4.w;
        nacc += x4.x * x4.x + x4.y * x4.y + x4.z * x4.z + x4.w * x4.w;
    }
    Sred[cg][pq] = Sacc;
    nacc = warpReduce(nacc);
    if (lane == 0) nsh[wid] = nacc;
    __syncthreads();
    if (t < 8) {
        float4 s = make_float4(0.f, 0.f, 0.f, 0.f);
        #pragma unroll
        for (int g2 = 0; g2 < 32; g2++) {
            float4 a = Sred[g2][t];
            s.x += a.x; s.y += a.y; s.z += a.z; s.w += a.w;
        }
        Ssm[t] = s;
    }
    if (t == 8) {
        float s = 0.f;
        #pragma unroll
        for (int w2 = 0; w2 < 8; w2++) s += nsh[w2];
        g_npart[b][blockIdx.x] = s;
    }
    __syncthreads();
    float4 S4 = Ssm[pq];
    #pragma unroll
    for (int i = 0; i < 8; i++) {
        size_t off = base + (size_t)(cg + 32 * i) * HW;
        float4 s4 = *(const float4*)(s0 + off);          // L2-hot
        float rx = s4.x * (xv[i].x - S4.x), ry = s4.y * (xv[i].y - S4.y);
        float rz = s4.z * (xv[i].z - S4.z), rw = s4.w * (xv[i].w - S4.w);
        *(uint2*)(g_Rhi + off)    = make_uint2(pack_hi(rx, ry), pack_hi(rz, rw));
        *(uint2*)(g_Rlo + off)    = make_uint2(pack_lo(rx, ry), pack_lo(rz, rw));
        *(uint2*)(g_Qbf[0] + off) = make_uint2(pack_hi(xv[i].x, xv[i].y), pack_hi(xv[i].z, xv[i].w));
    }
}

// ---------------- fused update + replicator + dots_fin + norm (k = 0..6) ----------------
__global__ void __launch_bounds__(256, 2) k_upd_repl(const float* __restrict__ s0,
                                                     const float* __restrict__ v, int k, int b) {
    const int t = threadIdx.x, lane = t & 31, wid = t >> 5;
    const int pq = t & 7;
    const int cg = t >> 3;
    const int p0 = blockIdx.x * 32;
    const size_t base = (size_t)b * PER_B + p0 + pq * 4;

    __shared__ float  hc[8];
    __shared__ float4 Sred[32][8];
    __shared__ float4 Ssm[8];
    __shared__ float  nsh[8];

    // inline dots finalize: warp j (j<=k<=6, 8 warps) reduces 64 partials -> hcoef
    if (wid <= k) {
        float dv = g_dpart[wid][b][lane] + g_dpart[wid][b][lane + 32];
        dv = warpReduce(dv);
        if (lane == 0) {
            float invj = g_inv[wid][b];
            float h = dv * invj;
            hc[wid] = h * invj;
            if (blockIdx.x == 0) g_H[b][wid][k] = h;
        }
    }
    __syncthreads();

    float4 xv[8];
    #pragma unroll
    for (int i = 0; i < 8; i++) {
        size_t off = base + (size_t)(cg + 32 * i) * HW;
        xv[i] = __ldcs((const float4*)(g_w + off));      // single-use stream: evict-first
    }
    for (int j = 0; j <= k; j++) {
        const float* __restrict__ Qj = (j == 0) ? v : g_Q[j - 1];
        float cf = hc[j];
        #pragma unroll
        for (int i = 0; i < 8; i++) {
            size_t off = base + (size_t)(cg + 32 * i) * HW;
            float4 q = *(const float4*)(Qj + off);
            xv[i].x -= cf * q.x; xv[i].y -= cf * q.y;
            xv[i].z -= cf * q.z; xv[i].w -= cf * q.w;
        }
    }

    float* __restrict__ qn = g_Q[k];                     // slot k = Q_{k+1} (skipped for k==6)
    __nv_bfloat16* __restrict__ qb = g_Qbf[k + 1];
    const bool write_q32 = (k < 6);
    float4 Sacc = make_float4(0.f, 0.f, 0.f, 0.f);
    float nacc = 0.f;
    #pragma unroll
    for (int i = 0; i < 8; i++) {
        size_t off = base + (size_t)(cg + 32 * i) * HW;
        if (write_q32) *(float4*)(qn + off) = xv[i];
        *(uint2*)(qb + off)  = make_uint2(pack_hi(xv[i].x, xv[i].y), pack_hi(xv[i].z, xv[i].w));
        float4 s4 = *(const float4*)(s0 + off);
        Sacc.x += s4.x * xv[i].x; Sacc.y += s4.y * xv[i].y;
        Sacc.z += s4.z * xv[i].z; Sacc.w += s4.w * xv[i].w;
        nacc += xv[i].x * xv[i].x + xv[i].y * xv[i].y
              + xv[i].z * xv[i].z + xv[i].w * xv[i].w;
    }
    Sred[cg][pq] = Sacc;
    nacc = warpReduce(nacc);
    if (lane == 0) nsh[wid] = nacc;
    __syncthreads();
    if (t < 8) {
        float4 s = make_float4(0.f, 0.f, 0.f, 0.f);
        #pragma unroll
        for (int g2 = 0; g2 < 32; g2++) {
            float4 a = Sred[g2][t];
            s.x += a.x; s.y += a.y; s.z += a.z; s.w += a.w;
        }
        Ssm[t] = s;
    }
    if (t == 8) {
        float s = 0.f;
        #pragma unroll
        for (int w2 = 0; w2 < 8; w2++) s += nsh[w2];
        g_npart[b][blockIdx.x] = s;
    }
    __syncthreads();
    float4 S4 = Ssm[pq];
    #pragma unroll
    for (int i = 0; i < 8; i++) {
        size_t off = base + (size_t)(cg + 32 * i) * HW;
        float4 s4 = *(const float4*)(s0 + off);          // L2-hot re-read
        float rx = s4.x * (xv[i].x - S4.x), ry = s4.y * (xv[i].y - S4.y);
        float rz = s4.z * (xv[i].z - S4.z), rw = s4.w * (xv[i].w - S4.w);
        *(uint2*)(g_Rhi + off) = make_uint2(pack_hi(rx, ry), pack_hi(rz, rw));
        *(uint2*)(g_Rlo + off) = make_uint2(pack_lo(rx, ry), pack_lo(rz, rw));
    }
}

// ---------------- fused GEMM + dots (2-stage pipeline, bf16 dot reads, inline norm finalize) ----------------
static __device__ __forceinline__ void cp_tileA(uint32_t dstbase, const __nv_bfloat16* src,
                                                int kc, int tid) {
    #pragma unroll
    for (int i = 0; i < 2; i++) {
        int x   = tid + (i << 8);     // 0..511 16B chunks
        int row = x >> 2;             // 0..127
        int cb  = (x & 3) << 4;       // 0,16,32,48
        const char* gp = (const char*)(src + (size_t)row * 256 + kc) + cb;
        uint32_t dp = dstbase + (uint32_t)(row * 64 + (cb ^ (((row >> 1) & 3) << 4)));
        CP16(dp, gp);
    }
}
static __device__ __forceinline__ void cp_tileB(uint32_t dstbase, const __nv_bfloat16* srcb,
                                                int kc, int tid) {
    #pragma unroll
    for (int i = 0; i < 2; i++) {
        int x   = tid + (i << 8);     // 0..511
        int row = x >> 4;             // 0..31 (c within chunk)
        int cb  = (x & 15) << 4;      // byte col 0..240
        const char* gp = (const char*)(srcb + (size_t)(kc + row) * HW) + cb;
        CP16(dstbase + (uint32_t)(row * 272 + cb), gp);
    }
}

#define STG_SZ 33792   // per-stage: AH 8192 + AL 8192 + BH 8704 + BL 8704

__global__ void __launch_bounds__(256, 2) k_gemm_fused(const float* __restrict__ v,
                                                       int kstep, int write_w, int b, int full3) {
    extern __shared__ __align__(128) char smem[];
    const int tid  = threadIdx.x;
    const int wid  = tid >> 5;
    const int lane = tid & 31;
    const int g    = lane >> 2;
    const int q    = lane & 3;
    const int l8   = lane & 7;
    const int g8   = lane >> 3;
    const int wm   = wid >> 2;       // 0..1
    const int wn   = wid & 3;        // 0..3
    const int p0   = blockIdx.x * 128;
    const int mt   = blockIdx.y;

    uint32_t sb = smem_u32(smem);

    const __nv_bfloat16* Whi = g_Whi + (size_t)mt * 128 * 256;
    const __nv_bfloat16* Wlo = g_Wlo + (size_t)mt * 128 * 256;
    const __nv_bfloat16* RhiB = g_Rhi + (size_t)b * PER_B + p0;
    const __nv_bfloat16* RloB = g_Rlo + (size_t)b * PER_B + p0;
    const size_t qtile = (size_t)b * PER_B + (size_t)(mt * 128) * HW + p0;

    // prologue: chunk 0 into stage 0
    cp_tileA(sb,         Whi,  0, tid);
    cp_tileB(sb + 16384, RhiB, 0, tid);
    if (full3) {
        cp_tileA(sb + 8192,  Wlo,  0, tid);
        cp_tileB(sb + 25088, RloB, 0, tid);
    }
    CP_COMMIT();

    // inline norm finalize -> inv_k (overlaps chunk-0 load); 128 partials
    __shared__ float invsh;
    __shared__ float rsh[4];
    if (tid < 128) {
        float val = warpReduce(g_npart[b][tid]);
        if (lane == 0) rsh[wid] = val;
    }
    __syncthreads();
    if (tid == 0) {
        float hn = sqrtf(rsh[0] + rsh[1] + rsh[2] + rsh[3]);
        float iv = (kstep == 0) ? (1.f / hn) : (1.f / (hn + EPSF));
        invsh = iv;
        if (blockIdx.x == 0 && blockIdx.y == 0) {
            g_inv[kstep][b] = iv;
            if (kstep == 0) g_vnorm[b] = hn;
            else            g_H[b][kstep][kstep - 1] = hn;
        }
    }

    float acc[4][4][4];
    #pragma unroll
    for (int i = 0; i < 4; i++)
        #pragma unroll
        for (int j = 0; j < 4; j++)
            #pragma unroll
            for (int e = 0; e < 4; e++) acc[i][j][e] = 0.f;

    const uint32_t aR0 = (uint32_t)(wm * 64 + (g8 & 1) * 8 + l8);
    const uint32_t aK  = (uint32_t)(g8 >> 1) << 4;
    const uint32_t bRow = (uint32_t)(((lane >> 3) & 1) * 8 + l8);
    const uint32_t bCol = (uint32_t)(wn * 64) + ((uint32_t)(lane >> 4)) * 16;

    #pragma unroll
    for (int ci = 0; ci < 8; ci++) {
        CP_WAIT0();
        __syncthreads();
        if (ci < 7) {
            uint32_t st = sb + (uint32_t)(((ci + 1) & 1) * STG_SZ);
            int kc = (ci + 1) * 32;
            cp_tileA(st,         Whi,  kc, tid);
            cp_tileB(st + 16384, RhiB, kc, tid);
            if (full3) {
                cp_tileA(st + 8192,  Wlo,  kc, tid);
                cp_tileB(st + 25088, RloB, kc, tid);
            }
            CP_COMMIT();
        }
        const uint32_t ST = sb + (uint32_t)((ci & 1) * STG_SZ);
        const uint32_t AHs = ST, ALs = ST + 8192, BHs = ST + 16384, BLs = ST + 25088;

        #pragma unroll
        for (int kf = 0; kf < 2; kf++) {
            const uint32_t cbA = (uint32_t)(kf * 32) + aK;
            uint32_t ah[4][4], al[4][4], bh[4][2], bl[4][2];
            #pragma unroll
            for (int mf = 0; mf < 4; mf++) {
                uint32_t r  = aR0 + (uint32_t)(mf * 16);
                uint32_t ao = r * 64 + (cbA ^ (((r >> 1) & 3) << 4));
                LDSM4(ah[mf][0], ah[mf][1], ah[mf][2], ah[mf][3], AHs + ao);
            }
            #pragma unroll
            for (int j2 = 0; j2 < 2; j2++) {
                uint32_t bo = (uint32_t)(kf * 16 + bRow) * 272 + bCol + (uint32_t)(j2 * 32);
                LDSM4T(bh[2*j2][0], bh[2*j2][1], bh[2*j2+1][0], bh[2*j2+1][1], BHs + bo);
            }
            #pragma unroll
            for (int mf = 0; mf < 4; mf++)
                #pragma unroll
                for (int nf = 0; nf < 4; nf++)
                    mma_bf16(acc[mf][nf], ah[mf], bh[nf]);   // Whi*Rhi
            if (full3) {
                #pragma unroll
                for (int mf = 0; mf < 4; mf++) {
                    uint32_t r  = aR0 + (uint32_t)(mf * 16);
                    uint32_t ao = r * 64 + (cbA ^ (((r >> 1) & 3) << 4));
                    LDSM4(al[mf][0], al[mf][1], al[mf][2], al[mf][3], ALs + ao);
                }
                #pragma unroll
                for (int j2 = 0; j2 < 2; j2++) {
                    uint32_t bo = (uint32_t)(kf * 16 + bRow) * 272 + bCol + (uint32_t)(j2 * 32);
                    LDSM4T(bl[2*j2][0], bl[2*j2][1], bl[2*j2+1][0], bl[2*j2+1][1], BLs + bo);
                }
                #pragma unroll
                for (int mf = 0; mf < 4; mf++)
                    #pragma unroll
                    for (int nf = 0; nf < 4; nf++) {
                        mma_bf16(acc[mf][nf], al[mf], bh[nf]);   // Wlo*Rhi
                        mma_bf16(acc[mf][nf], ah[mf], bl[nf]);   // Whi*Rlo
                    }
            }
        }
    }

    // scale by inv_k (deferred normalization of q_k)
    const float inv = invsh;
    #pragma unroll
    for (int mf = 0; mf < 4; mf++)
        #pragma unroll
        for (int nf = 0; nf < 4; nf++)
            #pragma unroll
            for (int e = 0; e < 4; e++) acc[mf][nf][e] *= inv;

    if (write_w) {
        float* dst = g_w + qtile;
        #pragma unroll
        for (int mf = 0; mf < 4; mf++) {
            int m = wm * 64 + mf * 16 + g;
            #pragma unroll
            for (int nf = 0; nf < 4; nf++) {
                int pp = wn * 32 + nf * 8 + q * 2;
                __stcs((float2*)(dst + (size_t)m * HW + pp),
                       make_float2(acc[mf][nf][0], acc[mf][nf][1]));
                __stcs((float2*)(dst + (size_t)(m + 8) * HW + pp),
                       make_float2(acc[mf][nf][2], acc[mf][nf][3]));
            }
        }
    }

    // fused dots vs bf16 Q mirror: raw partial <Qbf_j, w> over this CTA's 128x128 tile
    __shared__ float dsh[8][8];
    for (int j = 0; j <= kstep; j++) {
        const __nv_bfloat16* Qb = g_Qbf[j] + qtile;
        float d = 0.f;
        #pragma unroll
        for (int mf = 0; mf < 4; mf++) {
            int m = wm * 64 + mf * 16 + g;
            #pragma unroll
            for (int nf = 0; nf < 4; nf++) {
                int pp = wn * 32 + nf * 8 + q * 2;
                float2 a0 = __bfloat1622float2(*(const __nv_bfloat162*)(Qb + (size_t)m * HW + pp));
                float2 a1 = __bfloat1622float2(*(const __nv_bfloat162*)(Qb + (size_t)(m + 8) * HW + pp));
                d += acc[mf][nf][0] * a0.x + acc[mf][nf][1] * a0.y
                   + acc[mf][nf][2] * a1.x + acc[mf][nf][3] * a1.y;
            }
        }
        d = warpReduce(d);
        if (lane == 0) dsh[j][wid] = d;
    }
    __syncthreads();
    if (tid < 64) {
        int j = tid >> 3, w8 = tid & 7;
        float val = (j <= kstep) ? dsh[j][w8] : 0.f;
        #pragma unroll
        for (int off = 4; off > 0; off >>= 1) val += __shfl_xor_sync(0xFFFFFFFFu, val, off);
        if (w8 == 0 && j <= kstep) g_dpart[j][b][mt * 32 + blockIdx.x] = val;
    }
}

// ---------------- expm of 9x9 (scaling-squaring + Taylor, fp64) + H col 7 finalize ----------------
__global__ void k_expm(int b) {
    const int t = threadIdx.x;
    __shared__ double A[81], M[81], P[81], Pn[81];
    __shared__ float Hc7[8];
    __shared__ int ssc;

    if (t < 8) {
        float dv = 0.f;
        for (int i2 = 0; i2 < 64; i2++) dv += g_dpart[t][b][i2];
        Hc7[t] = dv * g_inv[t][b];
    }
    __syncthreads();

    if (t < 81) {
        int i = t / 9, j = t % 9;
        double e = 0.0;
        if (i < 8 && j < 8) e = (j == 7) ? (double)Hc7[i] : (double)g_H[b][i][j];
        if (i == 0 && j == 8) e = 1.0;
        A[t] = e;
    }
    __syncthreads();
    if (t == 0) {
        double nrm = 0.0;
        for (int i = 0; i < 9; i++) {
            double rs = 0.0;
            for (int j = 0; j < 9; j++) rs += fabs(A[i * 9 + j]);
            if (rs > nrm) nrm = rs;
        }
        int s = 0;
        while (nrm > 0.5 && s < 60) { nrm *= 0.5; s++; }
        ssc = s;
    }
    __syncthreads();
    const int s = ssc;
    if (t < 81) {
        A[t] = ldexp(A[t], -s);
        M[t] = ((t % 10 == 0) ? 1.0 : 0.0) + A[t];
        P[t] = A[t];
    }
    __syncthreads();
    for (int it = 2; it <= 22; it++) {
        if (t < 81) {
            int i = t / 9, j = t % 9;
            double acc = 0.0;
            #pragma unroll
            for (int kk = 0; kk < 9; kk++) acc += P[i * 9 + kk] * A[kk * 9 + j];
            Pn[t] = acc / (double)it;
        }
        __syncthreads();
        if (t < 81) { P[t] = Pn[t]; M[t] += P[t]; }
        __syncthreads();
    }
    for (int qq = 0; qq < s; qq++) {
        if (t < 81) {
            int i = t / 9, j = t % 9;
            double acc = 0.0;
            #pragma unroll
            for (int kk = 0; kk < 9; kk++) acc += M[i * 9 + kk] * M[kk * 9 + j];
            Pn[t] = acc;
        }
        __syncthreads();
        if (t < 81) M[t] = Pn[t];
        __syncthreads();
    }
    if (t < 8) {
        double coord = M[t * 9 + 8];
        g_cf[b][t] = (float)(coord * (double)g_vnorm[b] * (double)g_inv[t][b]);
    }
}

// ---------------- final combine (float4, fp32 Q for j<7, bf16 Qbf for j=7; per-batch) ----------------
__global__ void __launch_bounds__(256) k_combine(const float* __restrict__ v,
                                                 float* __restrict__ out, int b) {
    size_t idx = (size_t)b * PER_B + ((size_t)blockIdx.x * 256 + threadIdx.x) * 4;
    float cf[8];
    #pragma unroll
    for (int j = 0; j < 8; j++) cf[j] = g_cf[b][j];
    float4 x = make_float4(0.f, 0.f, 0.f, 0.f);
    #pragma unroll
    for (int j = 0; j < 7; j++) {
        const float* qs = (j == 0) ? v : g_Q[j - 1];
        float4 q = *(const float4*)(qs + idx);
        x.x += cf[j] * q.x; x.y += cf[j] * q.y;
        x.z += cf[j] * q.z; x.w += cf[j] * q.w;
    }
    {   // j = 7 from bf16 mirror
        uint2 p = *(const uint2*)(g_Qbf[7] + idx);
        float2 a0 = __bfloat1622float2(*(const __nv_bfloat162*)&p.x);
        float2 a1 = __bfloat1622float2(*(const __nv_bfloat162*)&p.y);
        x.x += cf[7] * a0.x; x.y += cf[7] * a0.y;
        x.z += cf[7] * a1.x; x.w += cf[7] * a1.y;
    }
    *(float4*)(out + idx) = x;
}

// dummy join kernel (makes the final join visible to the captured graph cheaply)
__global__ void k_nop() {}

// ---------------- driver: 8 streams x 1 batch, phase-staggered, fork/join via events ----------------
extern "C" void kernel_launch(void* const* d_in, const int* in_sizes, int n_in,
                              void* d_out, int out_size) {
    const float* s0 = (const float*)d_in[0];
    const float* v  = (const float*)d_in[1];
    const float* Wm = (const float*)d_in[2];
    float* out = (float*)d_out;

    const int GEMM_SMEM = 2 * STG_SZ;   // 67584
    cudaFuncSetAttribute(k_gemm_fused, cudaFuncAttributeMaxDynamicSharedMemorySize, GEMM_SMEM);

    dim3 gP(HW / 32);                // per-batch: 128 p-tiles
    dim3 gGemm(HW / 128, 2);         // per-batch: 32 p-tiles x 2 m-tiles
    dim3 gComb(PER_B / 1024);        // per-batch combine

    k_splitW<<<Cc * Cc / 256, 256>>>(Wm);
    cudaEventRecord(g_si.root, 0);

    for (int s = 0; s < 8; s++) {
        cudaStream_t st = g_si.st[s];
        const int b = s;
        cudaStreamWaitEvent(st, g_si.root, 0);
        k_repl0<<<gP, 256, 0, st>>>(s0, v, b);
        // phase stagger: streams 4..7 start their GEMM chain one gemm-phase later
        if (s >= 4) cudaStreamWaitEvent(st, g_si.stg[s - 4], 0);
        for (int k = 0; k < 8; k++) {
            int full3 = (k < 7) ? 1 : 0;
            k_gemm_fused<<<gGemm, 256, GEMM_SMEM, st>>>(v, k, (k < 7) ? 1 : 0, b, full3);
            if (s < 4 && k == 0) cudaEventRecord(g_si.stg[s], st);
            if (k < 7) k_upd_repl<<<gP, 256, 0, st>>>(s0, v, k, b);
        }
        k_expm<<<1, 128, 0, st>>>(b);
        k_combine<<<gComb, 256, 0, st>>>(v, out, b);
        cudaEventRecord(g_si.join[s], st);
    }

    for (int s = 0; s < 8; s++) cudaStreamWaitEvent(0, g_si.join[s], 0);
    k_nop<<<1, 32>>>();
}